// round 1
// baseline (speedup 1.0000x reference)
#include <cuda_runtime.h>
#include <math.h>

// Problem constants
#define Bq 8
#define Tq 2048
#define Dq 1024
#define Hq 16
#define Kq 64
#define Mq (Bq*Tq)                 // 16384 rows
#define BTDq ((size_t)Mq*(size_t)Dq)

// ---------------- scratch (device globals; no allocations allowed) -------------
__device__ float g_dx  [Mq*Dq];
__device__ float g_xxx [Mq*Dq];
__device__ float g_t5  [Mq*160];
__device__ float g_xw  [Mq*Dq];
__device__ float g_xk  [Mq*Dq];
__device__ float g_xv  [Mq*Dq];
__device__ float g_xr  [Mq*Dq];
__device__ float g_xg  [Mq*Dq];
__device__ float g_r   [Mq*Dq];
__device__ float g_k   [Mq*Dq];
__device__ float g_v   [Mq*Dq];
__device__ float g_g   [Mq*Dq];
__device__ float g_hbuf[Mq*64];
__device__ float g_ww  [Mq*Dq];
__device__ float g_gate[Mq*Dq];
__device__ float g_yf  [Mq*Dq];
__device__ float g_yb  [Mq*Dq];
__device__ float g_z   [Mq*Dq];

// ---------------- kernel 1: depthwise conv (k=3), dx, xxx ---------------------
__global__ void conv_kernel(const float* __restrict__ x,
                            const float* __restrict__ cw,
                            const float* __restrict__ maa_x)
{
    size_t idx = (size_t)blockIdx.x * blockDim.x + threadIdx.x;
    if (idx >= BTDq) return;
    int d = (int)(idx & (Dq - 1));
    int t = (int)((idx / Dq) & (Tq - 1));
    float x0 = x[idx];
    float xm = (t > 0)      ? x[idx - Dq] : 0.f;
    float xp = (t < Tq - 1) ? x[idx + Dq] : 0.f;
    float dxv = cw[d*3+0]*xm + cw[d*3+1]*x0 + cw[d*3+2]*xp - x0;
    g_dx[idx]  = dxv;
    g_xxx[idx] = x0 + dxv * maa_x[d];
}

// ---------------- generic SGEMM with fused epilogues ---------------------------
// C[M,N] = A[M,K] * B[K,N], all row-major (arbitrary leading dims).
#define BMt 128
#define BNt 128
#define BKt 16

enum { EPI_NONE = 0, EPI_TANH, EPI_SILU, EPI_MIX, EPI_DECAY, EPI_GATE };

template<int EPI>
__device__ __forceinline__ float epi_apply(float acc, int row, int col, int ldc,
                                           const float* __restrict__ vec,
                                           const float* __restrict__ auxX,
                                           const float* __restrict__ auxDX)
{
    if (EPI == EPI_TANH)  return tanhf(acc);
    if (EPI == EPI_SILU)  return acc / (1.f + __expf(-acc));
    if (EPI == EPI_MIX) {
        size_t idx = (size_t)row * ldc + col;
        return auxX[idx] + auxDX[idx] * (vec[col] + acc);
    }
    if (EPI == EPI_DECAY) return __expf(-__expf(vec[col] + acc));
    if (EPI == EPI_GATE)  return 1.f / (1.f + __expf(-(acc + vec[col])));
    return acc;
}

template<int EPI>
__global__ void __launch_bounds__(256, 2) sgemm(
    const float* __restrict__ A, int lda,
    const float* __restrict__ Bm, int ldb,
    float* __restrict__ C, int ldc,
    int N, int Kd,
    const float* __restrict__ vec,
    const float* __restrict__ auxX,
    const float* __restrict__ auxDX)
{
    __shared__ float As[BKt][BMt];
    __shared__ float Bs[BKt][BNt];

    int tid = threadIdx.x;
    int m0  = blockIdx.y * BMt;
    int n0  = blockIdx.x * BNt;

    int a_row = tid >> 2;            // 0..63 (2 rows: +0, +64)
    int a_col = (tid & 3) << 2;      // 0,4,8,12
    int b_row = tid >> 5;            // 0..7 (2 rows: +0, +8)
    int b_col = (tid & 31) << 2;     // 0..124
    int ty = tid >> 4, tx = tid & 15;

    const float* Aptr = A + (size_t)m0 * lda;
    bool bvalid = (n0 + b_col) < N;
    const float4 z4 = make_float4(0.f, 0.f, 0.f, 0.f);

    float4 a_reg[2], b_reg[2];

    // prologue: tile 0
    a_reg[0] = *(const float4*)(Aptr + (size_t)a_row       * lda + a_col);
    a_reg[1] = *(const float4*)(Aptr + (size_t)(a_row + 64) * lda + a_col);
    b_reg[0] = bvalid ? *(const float4*)(Bm + (size_t)b_row       * ldb + n0 + b_col) : z4;
    b_reg[1] = bvalid ? *(const float4*)(Bm + (size_t)(b_row + 8) * ldb + n0 + b_col) : z4;

    #pragma unroll
    for (int jj = 0; jj < 4; jj++) {
        As[a_col + jj][a_row]      = ((const float*)&a_reg[0])[jj];
        As[a_col + jj][a_row + 64] = ((const float*)&a_reg[1])[jj];
    }
    *(float4*)&Bs[b_row][b_col]     = b_reg[0];
    *(float4*)&Bs[b_row + 8][b_col] = b_reg[1];
    __syncthreads();

    float acc[8][8];
    #pragma unroll
    for (int i = 0; i < 8; i++)
        #pragma unroll
        for (int j = 0; j < 8; j++)
            acc[i][j] = 0.f;

    for (int k0 = 0;;) {
        int knext = k0 + BKt;
        if (knext < Kd) {
            a_reg[0] = *(const float4*)(Aptr + (size_t)a_row       * lda + knext + a_col);
            a_reg[1] = *(const float4*)(Aptr + (size_t)(a_row + 64) * lda + knext + a_col);
            b_reg[0] = bvalid ? *(const float4*)(Bm + (size_t)(knext + b_row)     * ldb + n0 + b_col) : z4;
            b_reg[1] = bvalid ? *(const float4*)(Bm + (size_t)(knext + b_row + 8) * ldb + n0 + b_col) : z4;
        }
        #pragma unroll
        for (int kk = 0; kk < BKt; kk++) {
            float a_f[8], b_f[8];
            *(float4*)&a_f[0] = *(const float4*)&As[kk][ty * 8];
            *(float4*)&a_f[4] = *(const float4*)&As[kk][ty * 8 + 4];
            *(float4*)&b_f[0] = *(const float4*)&Bs[kk][tx * 8];
            *(float4*)&b_f[4] = *(const float4*)&Bs[kk][tx * 8 + 4];
            #pragma unroll
            for (int i = 0; i < 8; i++)
                #pragma unroll
                for (int j = 0; j < 8; j++)
                    acc[i][j] = fmaf(a_f[i], b_f[j], acc[i][j]);
        }
        if (knext >= Kd) break;
        __syncthreads();
        #pragma unroll
        for (int jj = 0; jj < 4; jj++) {
            As[a_col + jj][a_row]      = ((const float*)&a_reg[0])[jj];
            As[a_col + jj][a_row + 64] = ((const float*)&a_reg[1])[jj];
        }
        *(float4*)&Bs[b_row][b_col]     = b_reg[0];
        *(float4*)&Bs[b_row + 8][b_col] = b_reg[1];
        __syncthreads();
        k0 = knext;
    }

    // epilogue + store
    #pragma unroll
    for (int i = 0; i < 8; i++) {
        int row = m0 + ty * 8 + i;
        #pragma unroll
        for (int j = 0; j < 8; j += 4) {
            int col = n0 + tx * 8 + j;
            if (col < N) {
                float4 o;
                o.x = epi_apply<EPI>(acc[i][j + 0], row, col + 0, ldc, vec, auxX, auxDX);
                o.y = epi_apply<EPI>(acc[i][j + 1], row, col + 1, ldc, vec, auxX, auxDX);
                o.z = epi_apply<EPI>(acc[i][j + 2], row, col + 2, ldc, vec, auxX, auxDX);
                o.w = epi_apply<EPI>(acc[i][j + 3], row, col + 3, ldc, vec, auxX, auxDX);
                *(float4*)&C[(size_t)row * ldc + col] = o;
            }
        }
    }
}

// ---------------- bidirectional WKV recurrence ---------------------------------
// grid: (B*H, 2), 64 threads. Thread j owns column j of the 64x64 state.
__global__ void __launch_bounds__(64) wkv_kernel()
{
    int bh  = blockIdx.x;
    int dir = blockIdx.y;
    int b = bh / Hq, h = bh % Hq;
    size_t base = (size_t)b * Tq * Dq + (size_t)h * Kq;
    int j = threadIdx.x;

    __shared__ float s_r[2][Kq], s_k[2][Kq], s_w[2][Kq];

    float S[Kq];
    #pragma unroll
    for (int i = 0; i < Kq; i++) S[i] = 0.f;

    if (dir == 0) {
        for (int t = 0; t < Tq; t++) {
            size_t off = base + (size_t)t * Dq;
            int buf = t & 1;
            s_r[buf][j] = g_r[off + j];
            s_k[buf][j] = g_k[off + j];
            s_w[buf][j] = g_ww[off + j];
            __syncthreads();
            float vj = g_v[off + j];
            float y0 = 0.f, y1 = 0.f, y2 = 0.f, y3 = 0.f;
            const float4* r4 = (const float4*)s_r[buf];
            const float4* k4 = (const float4*)s_k[buf];
            const float4* w4 = (const float4*)s_w[buf];
            #pragma unroll
            for (int i4 = 0; i4 < Kq / 4; i4++) {
                float4 rv = r4[i4], kv = k4[i4], wv = w4[i4];
                float* Sp = &S[i4 * 4];
                Sp[0] = fmaf(wv.x, Sp[0], kv.x * vj); y0 = fmaf(rv.x, Sp[0], y0);
                Sp[1] = fmaf(wv.y, Sp[1], kv.y * vj); y1 = fmaf(rv.y, Sp[1], y1);
                Sp[2] = fmaf(wv.z, Sp[2], kv.z * vj); y2 = fmaf(rv.z, Sp[2], y2);
                Sp[3] = fmaf(wv.w, Sp[3], kv.w * vj); y3 = fmaf(rv.w, Sp[3], y3);
            }
            g_yf[off + j] = (y0 + y1) + (y2 + y3);
        }
    } else {
        for (int tt = 0; tt < Tq; tt++) {
            int t = Tq - 1 - tt;
            size_t off = base + (size_t)t * Dq;
            int buf = tt & 1;
            s_r[buf][j] = g_r[off + j];
            s_k[buf][j] = g_k[off + j];
            s_w[buf][j] = g_ww[off + j];
            __syncthreads();
            float vj = g_v[off + j];
            float y0 = 0.f, y1 = 0.f, y2 = 0.f, y3 = 0.f;
            const float4* r4 = (const float4*)s_r[buf];
            const float4* k4 = (const float4*)s_k[buf];
            const float4* w4 = (const float4*)s_w[buf];
            #pragma unroll
            for (int i4 = 0; i4 < Kq / 4; i4++) {
                float4 rv = r4[i4], kv = k4[i4], wv = w4[i4];
                float* Sp = &S[i4 * 4];
                y0 = fmaf(rv.x, Sp[0], y0); Sp[0] = wv.x * fmaf(kv.x, vj, Sp[0]);
                y1 = fmaf(rv.y, Sp[1], y1); Sp[1] = wv.y * fmaf(kv.y, vj, Sp[1]);
                y2 = fmaf(rv.z, Sp[2], y2); Sp[2] = wv.z * fmaf(kv.z, vj, Sp[2]);
                y3 = fmaf(rv.w, Sp[3], y3); Sp[3] = wv.w * fmaf(kv.w, vj, Sp[3]);
            }
            g_yb[off + j] = (y0 + y1) + (y2 + y3);
        }
    }
}

// ---------------- groupnorm + output gate + silu-gate --------------------------
// one warp per (b,t,h) group of 64; 4 warps / block
__global__ void __launch_bounds__(128) gn_kernel(const float* __restrict__ ln_w,
                                                 const float* __restrict__ ln_b)
{
    int gidx = blockIdx.x * 4 + (threadIdx.x >> 5);   // 0 .. B*T*H-1
    int lane = threadIdx.x & 31;
    int bt = gidx / Hq, h = gidx % Hq;
    size_t rowbase = (size_t)bt * Dq + (size_t)h * Kq;
    size_t i0 = rowbase + lane, i1 = rowbase + lane + 32;

    float a = (g_yf[i0] + g_yb[i0]) * g_gate[i0];
    float c = (g_yf[i1] + g_yb[i1]) * g_gate[i1];
    float s = a + c, sq = a * a + c * c;
    #pragma unroll
    for (int o = 16; o; o >>= 1) {
        s  += __shfl_xor_sync(0xffffffffu, s,  o);
        sq += __shfl_xor_sync(0xffffffffu, sq, o);
    }
    float mean = s * (1.f / 64.f);
    float var  = sq * (1.f / 64.f) - mean * mean;
    float rstd = rsqrtf(var + 6.4e-4f);   // eps = 1e-5 * 8^2
    int d0 = h * Kq + lane, d1 = d0 + 32;
    g_z[i0] = ((a - mean) * rstd * ln_w[d0] + ln_b[d0]) * g_g[i0];
    g_z[i1] = ((c - mean) * rstd * ln_w[d1] + ln_b[d1]) * g_g[i1];
}

// ---------------- launch --------------------------------------------------------
extern "C" void kernel_launch(void* const* d_in, const int* in_sizes, int n_in,
                              void* d_out, int out_size)
{
    const float* x          = (const float*)d_in[0];
    const float* conv_w     = (const float*)d_in[1];
    const float* maa_x      = (const float*)d_in[2];
    const float* maa_w      = (const float*)d_in[3];
    const float* maa_k      = (const float*)d_in[4];
    const float* maa_v      = (const float*)d_in[5];
    const float* maa_r      = (const float*)d_in[6];
    const float* maa_g      = (const float*)d_in[7];
    const float* maa_w1     = (const float*)d_in[8];
    const float* maa_w2     = (const float*)d_in[9];
    const float* time_decay = (const float*)d_in[10];
    const float* decay_w1   = (const float*)d_in[11];
    const float* decay_w2   = (const float*)d_in[12];
    const float* Wr         = (const float*)d_in[13];
    const float* Wk         = (const float*)d_in[14];
    const float* Wv         = (const float*)d_in[15];
    const float* Wg         = (const float*)d_in[16];
    const float* Wo         = (const float*)d_in[17];
    const float* ln_w       = (const float*)d_in[18];
    const float* ln_b       = (const float*)d_in[19];
    const float* gate_w     = (const float*)d_in[20];
    const float* gate_b     = (const float*)d_in[21];
    float* out = (float*)d_out;

    float *p_dx, *p_xxx, *p_t5, *p_xw, *p_xk, *p_xv, *p_xr, *p_xg;
    float *p_r, *p_k, *p_v, *p_g, *p_h, *p_ww, *p_gate, *p_z;
    cudaGetSymbolAddress((void**)&p_dx,   g_dx);
    cudaGetSymbolAddress((void**)&p_xxx,  g_xxx);
    cudaGetSymbolAddress((void**)&p_t5,   g_t5);
    cudaGetSymbolAddress((void**)&p_xw,   g_xw);
    cudaGetSymbolAddress((void**)&p_xk,   g_xk);
    cudaGetSymbolAddress((void**)&p_xv,   g_xv);
    cudaGetSymbolAddress((void**)&p_xr,   g_xr);
    cudaGetSymbolAddress((void**)&p_xg,   g_xg);
    cudaGetSymbolAddress((void**)&p_r,    g_r);
    cudaGetSymbolAddress((void**)&p_k,    g_k);
    cudaGetSymbolAddress((void**)&p_v,    g_v);
    cudaGetSymbolAddress((void**)&p_g,    g_g);
    cudaGetSymbolAddress((void**)&p_h,    g_hbuf);
    cudaGetSymbolAddress((void**)&p_ww,   g_ww);
    cudaGetSymbolAddress((void**)&p_gate, g_gate);
    cudaGetSymbolAddress((void**)&p_z,    g_z);

    // 1) conv / dx / xxx
    {
        int threads = 256;
        int blocks  = (int)((BTDq + threads - 1) / threads);
        conv_kernel<<<blocks, threads>>>(x, conv_w, maa_x);
    }

    dim3 blk(256);
    dim3 grid_full(Dq / BNt, Mq / BMt);                 // N=1024
    dim3 grid_t5((160 + BNt - 1) / BNt, Mq / BMt);      // N=160
    dim3 grid_64(1, Mq / BMt);                          // N=64

    // 2) t5 = tanh(xxx @ maa_w1)
    sgemm<EPI_TANH><<<grid_t5, blk>>>(p_xxx, Dq, maa_w1, 160, p_t5, 160,
                                      160, Dq, nullptr, nullptr, nullptr);

    // 3) token-mix expansions: x + dx*(maa_c + t5_f @ maa_w2_f)
    const float* maas[5] = { maa_w, maa_k, maa_v, maa_r, maa_g };
    float* xouts[5]      = { p_xw, p_xk, p_xv, p_xr, p_xg };
    for (int f = 0; f < 5; f++) {
        sgemm<EPI_MIX><<<grid_full, blk>>>(p_t5 + f * 32, 160,
                                           maa_w2 + (size_t)f * 32 * Dq, Dq,
                                           xouts[f], Dq, Dq, 32,
                                           maas[f], x, p_dx);
    }

    // 4) big projections
    sgemm<EPI_NONE><<<grid_full, blk>>>(p_xr, Dq, Wr, Dq, p_r, Dq, Dq, Dq, nullptr, nullptr, nullptr);
    sgemm<EPI_NONE><<<grid_full, blk>>>(p_xk, Dq, Wk, Dq, p_k, Dq, Dq, Dq, nullptr, nullptr, nullptr);
    sgemm<EPI_NONE><<<grid_full, blk>>>(p_xv, Dq, Wv, Dq, p_v, Dq, Dq, Dq, nullptr, nullptr, nullptr);
    sgemm<EPI_SILU><<<grid_full, blk>>>(p_xg, Dq, Wg, Dq, p_g, Dq, Dq, Dq, nullptr, nullptr, nullptr);

    // 5) decay MLP: h = tanh(xw @ decay_w1); ww = exp(-exp(time_decay + h @ decay_w2))
    sgemm<EPI_TANH><<<grid_64, blk>>>(p_xw, Dq, decay_w1, 64, p_h, 64,
                                      64, Dq, nullptr, nullptr, nullptr);
    sgemm<EPI_DECAY><<<grid_full, blk>>>(p_h, 64, decay_w2, Dq, p_ww, Dq,
                                         Dq, 64, time_decay, nullptr, nullptr);

    // 6) output gate: sigmoid(dx @ gate_w + gate_b)
    sgemm<EPI_GATE><<<grid_full, blk>>>(p_dx, Dq, gate_w, Dq, p_gate, Dq,
                                        Dq, Dq, gate_b, nullptr, nullptr);

    // 7) bidirectional recurrence
    {
        dim3 g(Bq * Hq, 2);
        wkv_kernel<<<g, 64>>>();
    }

    // 8) gate + groupnorm + silu-gate
    gn_kernel<<<(Mq * Hq) / 4, 128>>>(ln_w, ln_b);

    // 9) out = z @ Wo
    sgemm<EPI_NONE><<<grid_full, blk>>>(p_z, Dq, Wo, Dq, out, Dq, Dq, Dq, nullptr, nullptr, nullptr);
}

// round 2
// speedup vs baseline: 1.0860x; 1.0860x over previous
#include <cuda_runtime.h>
#include <math.h>

// Problem constants
#define Bq 8
#define Tq 2048
#define Dq 1024
#define Hq 16
#define Kq 64
#define Mq (Bq*Tq)                 // 16384 rows
#define BTDq ((size_t)Mq*(size_t)Dq)

// ---------------- scratch (device globals; no allocations allowed) -------------
__device__ float g_dx  [Mq*Dq];
__device__ float g_xxx [Mq*Dq];
__device__ float g_t5  [Mq*160];
__device__ float g_xw  [Mq*Dq];
__device__ float g_xk  [Mq*Dq];
__device__ float g_xv  [Mq*Dq];
__device__ float g_xr  [Mq*Dq];
__device__ float g_xg  [Mq*Dq];
__device__ float g_r   [Mq*Dq];
__device__ float g_k   [Mq*Dq];
__device__ float g_v   [Mq*Dq];
__device__ float g_g   [Mq*Dq];
__device__ float g_hbuf[Mq*64];
__device__ float g_ww  [Mq*Dq];
__device__ float g_gate[Mq*Dq];
__device__ float g_yf  [Mq*Dq];
__device__ float g_yb  [Mq*Dq];
__device__ float g_z   [Mq*Dq];

// ---------------- packed f32x2 helpers (FFMA2 path, sm_103a) -------------------
__device__ __forceinline__ unsigned long long pk2(float lo, float hi) {
    unsigned long long r;
    asm("mov.b64 %0, {%1, %2};" : "=l"(r) : "f"(lo), "f"(hi));
    return r;
}
__device__ __forceinline__ void fma2(unsigned long long& d,
                                     unsigned long long a,
                                     unsigned long long b) {
    asm("fma.rn.f32x2 %0, %1, %2, %0;" : "+l"(d) : "l"(a), "l"(b));
}
__device__ __forceinline__ void unpk2(unsigned long long v, float& lo, float& hi) {
    asm("mov.b64 {%0, %1}, %2;" : "=f"(lo), "=f"(hi) : "l"(v));
}

// ---------------- kernel 1: depthwise conv (k=3), dx, xxx ---------------------
__global__ void conv_kernel(const float* __restrict__ x,
                            const float* __restrict__ cw,
                            const float* __restrict__ maa_x)
{
    size_t idx = (size_t)blockIdx.x * blockDim.x + threadIdx.x;
    if (idx >= BTDq) return;
    int d = (int)(idx & (Dq - 1));
    int t = (int)((idx / Dq) & (Tq - 1));
    float x0 = x[idx];
    float xm = (t > 0)      ? x[idx - Dq] : 0.f;
    float xp = (t < Tq - 1) ? x[idx + Dq] : 0.f;
    float dxv = cw[d*3+0]*xm + cw[d*3+1]*x0 + cw[d*3+2]*xp - x0;
    g_dx[idx]  = dxv;
    g_xxx[idx] = x0 + dxv * maa_x[d];
}

// ---------------- generic SGEMM with fused epilogues (FFMA2 inner loop) --------
// C[M,N] = A[M,K] * B[K,N], all row-major (arbitrary leading dims).
#define BMt 128
#define BNt 128
#define BKt 16

enum { EPI_NONE = 0, EPI_TANH, EPI_SILU, EPI_DECAY, EPI_GATE };

template<int EPI>
__device__ __forceinline__ float epi_apply(float acc, int col,
                                           const float* __restrict__ vec)
{
    if (EPI == EPI_TANH)  return tanhf(acc);
    if (EPI == EPI_SILU)  return acc / (1.f + __expf(-acc));
    if (EPI == EPI_DECAY) return __expf(-__expf(vec[col] + acc));
    if (EPI == EPI_GATE)  return 1.f / (1.f + __expf(-(acc + vec[col])));
    return acc;
}

template<int EPI>
__global__ void __launch_bounds__(256, 2) sgemm(
    const float* __restrict__ A, int lda,
    const float* __restrict__ Bm, int ldb,
    float* __restrict__ C, int ldc,
    int N, int Kd,
    const float* __restrict__ vec)
{
    __shared__ float As[BKt][BMt];
    __shared__ float Bs[BKt][BNt];

    int tid = threadIdx.x;
    int m0  = blockIdx.y * BMt;
    int n0  = blockIdx.x * BNt;

    int a_row = tid >> 2;            // 0..63 (2 rows: +0, +64)
    int a_col = (tid & 3) << 2;      // 0,4,8,12
    int b_row = tid >> 5;            // 0..7 (2 rows: +0, +8)
    int b_col = (tid & 31) << 2;     // 0..124
    int ty = tid >> 4, tx = tid & 15;

    const float* Aptr = A + (size_t)m0 * lda;
    bool bvalid = (n0 + b_col) < N;
    const float4 z4 = make_float4(0.f, 0.f, 0.f, 0.f);

    float4 a_reg[2], b_reg[2];

    // prologue: tile 0
    a_reg[0] = *(const float4*)(Aptr + (size_t)a_row       * lda + a_col);
    a_reg[1] = *(const float4*)(Aptr + (size_t)(a_row + 64) * lda + a_col);
    b_reg[0] = bvalid ? *(const float4*)(Bm + (size_t)b_row       * ldb + n0 + b_col) : z4;
    b_reg[1] = bvalid ? *(const float4*)(Bm + (size_t)(b_row + 8) * ldb + n0 + b_col) : z4;

    #pragma unroll
    for (int jj = 0; jj < 4; jj++) {
        As[a_col + jj][a_row]      = ((const float*)&a_reg[0])[jj];
        As[a_col + jj][a_row + 64] = ((const float*)&a_reg[1])[jj];
    }
    *(float4*)&Bs[b_row][b_col]     = b_reg[0];
    *(float4*)&Bs[b_row + 8][b_col] = b_reg[1];
    __syncthreads();

    unsigned long long acc2[8][4];
    #pragma unroll
    for (int i = 0; i < 8; i++)
        #pragma unroll
        for (int j = 0; j < 4; j++)
            acc2[i][j] = 0ull;

    for (int k0 = 0;;) {
        int knext = k0 + BKt;
        if (knext < Kd) {
            a_reg[0] = *(const float4*)(Aptr + (size_t)a_row       * lda + knext + a_col);
            a_reg[1] = *(const float4*)(Aptr + (size_t)(a_row + 64) * lda + knext + a_col);
            b_reg[0] = bvalid ? *(const float4*)(Bm + (size_t)(knext + b_row)     * ldb + n0 + b_col) : z4;
            b_reg[1] = bvalid ? *(const float4*)(Bm + (size_t)(knext + b_row + 8) * ldb + n0 + b_col) : z4;
        }
        #pragma unroll
        for (int kk = 0; kk < BKt; kk++) {
            float a_f[8], b_f[8];
            *(float4*)&a_f[0] = *(const float4*)&As[kk][ty * 8];
            *(float4*)&a_f[4] = *(const float4*)&As[kk][ty * 8 + 4];
            *(float4*)&b_f[0] = *(const float4*)&Bs[kk][tx * 8];
            *(float4*)&b_f[4] = *(const float4*)&Bs[kk][tx * 8 + 4];
            unsigned long long b2[4];
            #pragma unroll
            for (int j = 0; j < 4; j++) b2[j] = pk2(b_f[2*j], b_f[2*j+1]);
            #pragma unroll
            for (int i = 0; i < 8; i++) {
                unsigned long long a2 = pk2(a_f[i], a_f[i]);
                #pragma unroll
                for (int j = 0; j < 4; j++) fma2(acc2[i][j], a2, b2[j]);
            }
        }
        if (knext >= Kd) break;
        __syncthreads();
        #pragma unroll
        for (int jj = 0; jj < 4; jj++) {
            As[a_col + jj][a_row]      = ((const float*)&a_reg[0])[jj];
            As[a_col + jj][a_row + 64] = ((const float*)&a_reg[1])[jj];
        }
        *(float4*)&Bs[b_row][b_col]     = b_reg[0];
        *(float4*)&Bs[b_row + 8][b_col] = b_reg[1];
        __syncthreads();
        k0 = knext;
    }

    // unpack accumulators
    float acc[8][8];
    #pragma unroll
    for (int i = 0; i < 8; i++)
        #pragma unroll
        for (int j = 0; j < 4; j++)
            unpk2(acc2[i][j], acc[i][2*j], acc[i][2*j+1]);

    // epilogue + store
    #pragma unroll
    for (int i = 0; i < 8; i++) {
        int row = m0 + ty * 8 + i;
        #pragma unroll
        for (int j = 0; j < 8; j += 4) {
            int col = n0 + tx * 8 + j;
            if (col < N) {
                float4 o;
                o.x = epi_apply<EPI>(acc[i][j + 0], col + 0, vec);
                o.y = epi_apply<EPI>(acc[i][j + 1], col + 1, vec);
                o.z = epi_apply<EPI>(acc[i][j + 2], col + 2, vec);
                o.w = epi_apply<EPI>(acc[i][j + 3], col + 3, vec);
                *(float4*)&C[(size_t)row * ldc + col] = o;
            }
        }
    }
}

// ---------------- fused 5-way token-mix kernel ---------------------------------
// For each f in 0..4: out_f = x + dx * (maa_f + t5_f @ maa_w2_f)
// Block tile: 64 rows x 128 cols; x/dx tiles are reused across f via L1/L2.
__global__ void __launch_bounds__(256) mix5_kernel(
    const float* __restrict__ maa_w2,
    const float* __restrict__ x,
    const float* __restrict__ mw, const float* __restrict__ mk,
    const float* __restrict__ mv, const float* __restrict__ mr,
    const float* __restrict__ mg)
{
    __shared__ float t5s[64][160];
    __shared__ float Bs[32][128];

    int m0 = blockIdx.y * 64;
    int n0 = blockIdx.x * 128;
    int tid = threadIdx.x;

    // stage t5 tile (64 x 160)
    for (int i = tid; i < 64 * 40; i += 256) {
        int r = i / 40, c4 = (i % 40) * 4;
        *(float4*)&t5s[r][c4] = *(const float4*)&g_t5[(size_t)(m0 + r) * 160 + c4];
    }

    int colg = (tid & 31) * 4;      // 0,4,...,124
    int row0 = (tid >> 5) * 8;      // 0,8,...,56

    const float* maas[5] = { mw, mk, mv, mr, mg };
    float* outs[5] = { g_xw, g_xk, g_xv, g_xr, g_xg };

    #pragma unroll
    for (int f = 0; f < 5; f++) {
        __syncthreads();
        // load B_f (32 x 128)
        for (int i = tid; i < 32 * 32; i += 256) {
            int k = i / 32, c4 = (i % 32) * 4;
            *(float4*)&Bs[k][c4] =
                *(const float4*)&maa_w2[((size_t)f * 32 + k) * Dq + n0 + c4];
        }
        __syncthreads();

        float acc0[8], acc1[8], acc2_[8], acc3[8];
        #pragma unroll
        for (int r = 0; r < 8; r++) { acc0[r]=0.f; acc1[r]=0.f; acc2_[r]=0.f; acc3[r]=0.f; }

        #pragma unroll 4
        for (int k = 0; k < 32; k++) {
            float4 b4 = *(const float4*)&Bs[k][colg];
            #pragma unroll
            for (int r = 0; r < 8; r++) {
                float a = t5s[row0 + r][f * 32 + k];
                acc0[r] = fmaf(a, b4.x, acc0[r]);
                acc1[r] = fmaf(a, b4.y, acc1[r]);
                acc2_[r] = fmaf(a, b4.z, acc2_[r]);
                acc3[r] = fmaf(a, b4.w, acc3[r]);
            }
        }

        float4 mva = *(const float4*)&maas[f][n0 + colg];
        float* op = outs[f];
        #pragma unroll
        for (int r = 0; r < 8; r++) {
            size_t idx = (size_t)(m0 + row0 + r) * Dq + n0 + colg;
            float4 xv4 = *(const float4*)&x[idx];
            float4 dx4 = *(const float4*)&g_dx[idx];
            float4 o;
            o.x = xv4.x + dx4.x * (mva.x + acc0[r]);
            o.y = xv4.y + dx4.y * (mva.y + acc1[r]);
            o.z = xv4.z + dx4.z * (mva.z + acc2_[r]);
            o.w = xv4.w + dx4.w * (mva.w + acc3[r]);
            *(float4*)&op[idx] = o;
        }
    }
}

// ---------------- bidirectional WKV recurrence ---------------------------------
// grid: (B*H, 2), 64 threads. Thread j owns column j of the 64x64 state.
__global__ void __launch_bounds__(64) wkv_kernel()
{
    int bh  = blockIdx.x;
    int dir = blockIdx.y;
    int b = bh / Hq, h = bh % Hq;
    size_t base = (size_t)b * Tq * Dq + (size_t)h * Kq;
    int j = threadIdx.x;

    __shared__ float s_r[2][Kq], s_k[2][Kq], s_w[2][Kq];

    float S[Kq];
    #pragma unroll
    for (int i = 0; i < Kq; i++) S[i] = 0.f;

    if (dir == 0) {
        for (int t = 0; t < Tq; t++) {
            size_t off = base + (size_t)t * Dq;
            int buf = t & 1;
            s_r[buf][j] = g_r[off + j];
            s_k[buf][j] = g_k[off + j];
            s_w[buf][j] = g_ww[off + j];
            __syncthreads();
            float vj = g_v[off + j];
            float y0 = 0.f, y1 = 0.f, y2 = 0.f, y3 = 0.f;
            const float4* r4 = (const float4*)s_r[buf];
            const float4* k4 = (const float4*)s_k[buf];
            const float4* w4 = (const float4*)s_w[buf];
            #pragma unroll
            for (int i4 = 0; i4 < Kq / 4; i4++) {
                float4 rv = r4[i4], kv = k4[i4], wv = w4[i4];
                float* Sp = &S[i4 * 4];
                Sp[0] = fmaf(wv.x, Sp[0], kv.x * vj); y0 = fmaf(rv.x, Sp[0], y0);
                Sp[1] = fmaf(wv.y, Sp[1], kv.y * vj); y1 = fmaf(rv.y, Sp[1], y1);
                Sp[2] = fmaf(wv.z, Sp[2], kv.z * vj); y2 = fmaf(rv.z, Sp[2], y2);
                Sp[3] = fmaf(wv.w, Sp[3], kv.w * vj); y3 = fmaf(rv.w, Sp[3], y3);
            }
            g_yf[off + j] = (y0 + y1) + (y2 + y3);
        }
    } else {
        for (int tt = 0; tt < Tq; tt++) {
            int t = Tq - 1 - tt;
            size_t off = base + (size_t)t * Dq;
            int buf = tt & 1;
            s_r[buf][j] = g_r[off + j];
            s_k[buf][j] = g_k[off + j];
            s_w[buf][j] = g_ww[off + j];
            __syncthreads();
            float vj = g_v[off + j];
            float y0 = 0.f, y1 = 0.f, y2 = 0.f, y3 = 0.f;
            const float4* r4 = (const float4*)s_r[buf];
            const float4* k4 = (const float4*)s_k[buf];
            const float4* w4 = (const float4*)s_w[buf];
            #pragma unroll
            for (int i4 = 0; i4 < Kq / 4; i4++) {
                float4 rv = r4[i4], kv = k4[i4], wv = w4[i4];
                float* Sp = &S[i4 * 4];
                y0 = fmaf(rv.x, Sp[0], y0); Sp[0] = wv.x * fmaf(kv.x, vj, Sp[0]);
                y1 = fmaf(rv.y, Sp[1], y1); Sp[1] = wv.y * fmaf(kv.y, vj, Sp[1]);
                y2 = fmaf(rv.z, Sp[2], y2); Sp[2] = wv.z * fmaf(kv.z, vj, Sp[2]);
                y3 = fmaf(rv.w, Sp[3], y3); Sp[3] = wv.w * fmaf(kv.w, vj, Sp[3]);
            }
            g_yb[off + j] = (y0 + y1) + (y2 + y3);
        }
    }
}

// ---------------- groupnorm + output gate + silu-gate --------------------------
__global__ void __launch_bounds__(128) gn_kernel(const float* __restrict__ ln_w,
                                                 const float* __restrict__ ln_b)
{
    int gidx = blockIdx.x * 4 + (threadIdx.x >> 5);   // 0 .. B*T*H-1
    int lane = threadIdx.x & 31;
    int bt = gidx / Hq, h = gidx % Hq;
    size_t rowbase = (size_t)bt * Dq + (size_t)h * Kq;
    size_t i0 = rowbase + lane, i1 = rowbase + lane + 32;

    float a = (g_yf[i0] + g_yb[i0]) * g_gate[i0];
    float c = (g_yf[i1] + g_yb[i1]) * g_gate[i1];
    float s = a + c, sq = a * a + c * c;
    #pragma unroll
    for (int o = 16; o; o >>= 1) {
        s  += __shfl_xor_sync(0xffffffffu, s,  o);
        sq += __shfl_xor_sync(0xffffffffu, sq, o);
    }
    float mean = s * (1.f / 64.f);
    float var  = sq * (1.f / 64.f) - mean * mean;
    float rstd = rsqrtf(var + 6.4e-4f);   // eps = 1e-5 * 8^2
    int d0 = h * Kq + lane, d1 = d0 + 32;
    g_z[i0] = ((a - mean) * rstd * ln_w[d0] + ln_b[d0]) * g_g[i0];
    g_z[i1] = ((c - mean) * rstd * ln_w[d1] + ln_b[d1]) * g_g[i1];
}

// ---------------- launch --------------------------------------------------------
extern "C" void kernel_launch(void* const* d_in, const int* in_sizes, int n_in,
                              void* d_out, int out_size)
{
    const float* x          = (const float*)d_in[0];
    const float* conv_w     = (const float*)d_in[1];
    const float* maa_x      = (const float*)d_in[2];
    const float* maa_w      = (const float*)d_in[3];
    const float* maa_k      = (const float*)d_in[4];
    const float* maa_v      = (const float*)d_in[5];
    const float* maa_r      = (const float*)d_in[6];
    const float* maa_g      = (const float*)d_in[7];
    const float* maa_w1     = (const float*)d_in[8];
    const float* maa_w2     = (const float*)d_in[9];
    const float* time_decay = (const float*)d_in[10];
    const float* decay_w1   = (const float*)d_in[11];
    const float* decay_w2   = (const float*)d_in[12];
    const float* Wr         = (const float*)d_in[13];
    const float* Wk         = (const float*)d_in[14];
    const float* Wv         = (const float*)d_in[15];
    const float* Wg         = (const float*)d_in[16];
    const float* Wo         = (const float*)d_in[17];
    const float* ln_w       = (const float*)d_in[18];
    const float* ln_b       = (const float*)d_in[19];
    const float* gate_w     = (const float*)d_in[20];
    const float* gate_b     = (const float*)d_in[21];
    float* out = (float*)d_out;

    float *p_dx, *p_xxx, *p_t5, *p_xw, *p_xk, *p_xv, *p_xr, *p_xg;
    float *p_r, *p_k, *p_v, *p_g, *p_h, *p_ww, *p_gate, *p_z;
    cudaGetSymbolAddress((void**)&p_dx,   g_dx);
    cudaGetSymbolAddress((void**)&p_xxx,  g_xxx);
    cudaGetSymbolAddress((void**)&p_t5,   g_t5);
    cudaGetSymbolAddress((void**)&p_xw,   g_xw);
    cudaGetSymbolAddress((void**)&p_xk,   g_xk);
    cudaGetSymbolAddress((void**)&p_xv,   g_xv);
    cudaGetSymbolAddress((void**)&p_xr,   g_xr);
    cudaGetSymbolAddress((void**)&p_xg,   g_xg);
    cudaGetSymbolAddress((void**)&p_r,    g_r);
    cudaGetSymbolAddress((void**)&p_k,    g_k);
    cudaGetSymbolAddress((void**)&p_v,    g_v);
    cudaGetSymbolAddress((void**)&p_g,    g_g);
    cudaGetSymbolAddress((void**)&p_h,    g_hbuf);
    cudaGetSymbolAddress((void**)&p_ww,   g_ww);
    cudaGetSymbolAddress((void**)&p_gate, g_gate);
    cudaGetSymbolAddress((void**)&p_z,    g_z);

    // 1) conv / dx / xxx
    {
        int threads = 256;
        int blocks  = (int)((BTDq + threads - 1) / threads);
        conv_kernel<<<blocks, threads>>>(x, conv_w, maa_x);
    }

    dim3 blk(256);
    dim3 grid_full(Dq / BNt, Mq / BMt);                 // N=1024
    dim3 grid_t5((160 + BNt - 1) / BNt, Mq / BMt);      // N=160
    dim3 grid_64(1, Mq / BMt);                          // N=64

    // 2) t5 = tanh(xxx @ maa_w1)
    sgemm<EPI_TANH><<<grid_t5, blk>>>(p_xxx, Dq, maa_w1, 160, p_t5, 160,
                                      160, Dq, nullptr);

    // 3) fused token-mix expansions: x + dx*(maa_c + t5_f @ maa_w2_f), f=0..4
    {
        dim3 g(Dq / 128, Mq / 64);
        mix5_kernel<<<g, 256>>>(maa_w2, x, maa_w, maa_k, maa_v, maa_r, maa_g);
    }

    // 4) big projections
    sgemm<EPI_NONE><<<grid_full, blk>>>(p_xr, Dq, Wr, Dq, p_r, Dq, Dq, Dq, nullptr);
    sgemm<EPI_NONE><<<grid_full, blk>>>(p_xk, Dq, Wk, Dq, p_k, Dq, Dq, Dq, nullptr);
    sgemm<EPI_NONE><<<grid_full, blk>>>(p_xv, Dq, Wv, Dq, p_v, Dq, Dq, Dq, nullptr);
    sgemm<EPI_SILU><<<grid_full, blk>>>(p_xg, Dq, Wg, Dq, p_g, Dq, Dq, Dq, nullptr);

    // 5) decay MLP: h = tanh(xw @ decay_w1); ww = exp(-exp(time_decay + h @ decay_w2))
    sgemm<EPI_TANH><<<grid_64, blk>>>(p_xw, Dq, decay_w1, 64, p_h, 64,
                                      64, Dq, nullptr);
    sgemm<EPI_DECAY><<<grid_full, blk>>>(p_h, 64, decay_w2, Dq, p_ww, Dq,
                                         Dq, 64, time_decay);

    // 6) output gate: sigmoid(dx @ gate_w + gate_b)
    sgemm<EPI_GATE><<<grid_full, blk>>>(p_dx, Dq, gate_w, Dq, p_gate, Dq,
                                        Dq, Dq, gate_b);

    // 7) bidirectional recurrence
    {
        dim3 g(Bq * Hq, 2);
        wkv_kernel<<<g, 64>>>();
    }

    // 8) gate + groupnorm + silu-gate
    gn_kernel<<<(Mq * Hq) / 4, 128>>>(ln_w, ln_b);

    // 9) out = z @ Wo
    sgemm<EPI_NONE><<<grid_full, blk>>>(p_z, Dq, Wo, Dq, out, Dq, Dq, Dq, nullptr);
}

// round 4
// speedup vs baseline: 1.6665x; 1.5345x over previous
#include <cuda_runtime.h>
#include <cuda_bf16.h>
#include <math.h>
#include <stdint.h>

// Problem constants
#define Bq 8
#define Tq 2048
#define Dq 1024
#define Hq 16
#define Kq 64
#define Mq (Bq*Tq)                 // 16384 rows
#define BTDq ((size_t)Mq*(size_t)Dq)

// ---------------- scratch (device globals; no allocations allowed) -------------
__device__ float g_dx  [Mq*Dq];
__device__ float g_xxx [Mq*Dq];
__device__ float g_t5  [Mq*160];
__device__ float g_xw  [Mq*Dq];
__device__ float g_r   [Mq*Dq];
__device__ float g_k   [Mq*Dq];
__device__ float g_v   [Mq*Dq];
__device__ float g_g   [Mq*Dq];
__device__ float g_hbuf[Mq*64];
__device__ float g_ww  [Mq*Dq];
__device__ float g_gate[Mq*Dq];
__device__ float g_yf  [Mq*Dq];
__device__ float g_yb  [Mq*Dq];

// bf16 hi/lo split activations
__device__ __nv_bfloat16 g_dxh[Mq*Dq], g_dxl[Mq*Dq];
__device__ __nv_bfloat16 g_xkh[Mq*Dq], g_xkl[Mq*Dq];
__device__ __nv_bfloat16 g_xvh[Mq*Dq], g_xvl[Mq*Dq];
__device__ __nv_bfloat16 g_xrh[Mq*Dq], g_xrl[Mq*Dq];
__device__ __nv_bfloat16 g_xgh[Mq*Dq], g_xgl[Mq*Dq];
__device__ __nv_bfloat16 g_zh [Mq*Dq], g_zl [Mq*Dq];
// transposed weights [N,K] hi/lo, 6 slots: Wr,Wk,Wv,Wg,gate_w,Wo
__device__ __nv_bfloat16 g_wh[6*1024*1024], g_wl[6*1024*1024];

// ---------------- helpers -------------------------------------------------------
__device__ __forceinline__ uint32_t smem_u32(const void* p) {
    uint32_t a;
    asm("{ .reg .u64 t; cvta.to.shared.u64 t, %1; cvt.u32.u64 %0, t; }" : "=r"(a) : "l"(p));
    return a;
}
__device__ __forceinline__ void cp16(uint32_t dst, const void* src) {
    asm volatile("cp.async.cg.shared.global [%0], [%1], 16;" :: "r"(dst), "l"(src));
}
#define CP_COMMIT() asm volatile("cp.async.commit_group;" ::: "memory")
#define CP_WAIT(n)  asm volatile("cp.async.wait_group %0;" :: "n"(n) : "memory")

#define LDSM4(R0, R1, R2, R3, ADDR) \
    asm volatile("ldmatrix.sync.aligned.m8n8.x4.shared.b16 {%0,%1,%2,%3}, [%4];" \
        : "=r"(R0), "=r"(R1), "=r"(R2), "=r"(R3) : "r"(ADDR))

#define MMA_BF16(D, A, B0, B1) \
    asm volatile("mma.sync.aligned.m16n8k16.row.col.f32.bf16.bf16.f32 " \
        "{%0,%1,%2,%3}, {%4,%5,%6,%7}, {%8,%9}, {%0,%1,%2,%3};" \
        : "+f"((D)[0]), "+f"((D)[1]), "+f"((D)[2]), "+f"((D)[3]) \
        : "r"((A)[0]), "r"((A)[1]), "r"((A)[2]), "r"((A)[3]), "r"(B0), "r"(B1))

// packed f32x2 helpers (FFMA2 path, small GEMMs)
__device__ __forceinline__ unsigned long long pk2(float lo, float hi) {
    unsigned long long r;
    asm("mov.b64 %0, {%1, %2};" : "=l"(r) : "f"(lo), "f"(hi));
    return r;
}
__device__ __forceinline__ void fma2(unsigned long long& d,
                                     unsigned long long a,
                                     unsigned long long b) {
    asm("fma.rn.f32x2 %0, %1, %2, %0;" : "+l"(d) : "l"(a), "l"(b));
}
__device__ __forceinline__ void unpk2(unsigned long long v, float& lo, float& hi) {
    asm("mov.b64 {%0, %1}, %2;" : "=f"(lo), "=f"(hi) : "l"(v));
}

// hi/lo split store of 4 consecutive floats
__device__ __forceinline__ void store_split4(__nv_bfloat16* H, __nv_bfloat16* L,
                                             size_t idx, float4 o) {
    __nv_bfloat162 h01 = __floats2bfloat162_rn(o.x, o.y);
    __nv_bfloat162 h23 = __floats2bfloat162_rn(o.z, o.w);
    float2 f01 = __bfloat1622float2(h01);
    float2 f23 = __bfloat1622float2(h23);
    __nv_bfloat162 l01 = __floats2bfloat162_rn(o.x - f01.x, o.y - f01.y);
    __nv_bfloat162 l23 = __floats2bfloat162_rn(o.z - f23.x, o.w - f23.y);
    uint2 hv = make_uint2(*(unsigned*)&h01, *(unsigned*)&h23);
    uint2 lv = make_uint2(*(unsigned*)&l01, *(unsigned*)&l23);
    *(uint2*)&H[idx] = hv;
    *(uint2*)&L[idx] = lv;
}

// ---------------- kernel: depthwise conv (k=3), dx (+hi/lo), xxx ---------------
__global__ void conv_kernel(const float* __restrict__ x,
                            const float* __restrict__ cw,
                            const float* __restrict__ maa_x)
{
    size_t idx = (size_t)blockIdx.x * blockDim.x + threadIdx.x;
    if (idx >= BTDq) return;
    int d = (int)(idx & (Dq - 1));
    int t = (int)((idx / Dq) & (Tq - 1));
    float x0 = x[idx];
    float xm = (t > 0)      ? x[idx - Dq] : 0.f;
    float xp = (t < Tq - 1) ? x[idx + Dq] : 0.f;
    float dxv = cw[d*3+0]*xm + cw[d*3+1]*x0 + cw[d*3+2]*xp - x0;
    g_dx[idx]  = dxv;
    g_xxx[idx] = x0 + dxv * maa_x[d];
    __nv_bfloat16 h = __float2bfloat16(dxv);
    g_dxh[idx] = h;
    g_dxl[idx] = __float2bfloat16(dxv - __bfloat162float(h));
}

// ---------------- kernel: weight transpose + bf16 split ------------------------
__global__ void __launch_bounds__(256) wsplit_kernel(
    const float* __restrict__ W0, const float* __restrict__ W1,
    const float* __restrict__ W2, const float* __restrict__ W3,
    const float* __restrict__ W4, const float* __restrict__ W5)
{
    __shared__ float tile[32][33];
    const float* Ws[6] = { W0, W1, W2, W3, W4, W5 };
    const float* W = Ws[blockIdx.z];
    __nv_bfloat16* H = g_wh + (size_t)blockIdx.z * 1024 * 1024;
    __nv_bfloat16* L = g_wl + (size_t)blockIdx.z * 1024 * 1024;
    int n0 = blockIdx.x * 32, k0 = blockIdx.y * 32;
    int tx = threadIdx.x & 31, ty = threadIdx.x >> 5;  // 32 x 8
    #pragma unroll
    for (int i = 0; i < 4; i++)
        tile[ty + i*8][tx] = W[(size_t)(k0 + ty + i*8) * 1024 + n0 + tx];
    __syncthreads();
    #pragma unroll
    for (int i = 0; i < 4; i++) {
        float v = tile[tx][ty + i*8];
        __nv_bfloat16 h = __float2bfloat16(v);
        size_t o = (size_t)(n0 + ty + i*8) * 1024 + k0 + tx;
        H[o] = h;
        L[o] = __float2bfloat16(v - __bfloat162float(h));
    }
}

// ---------------- HMMA bf16 split GEMM (mma.sync, base PTX) --------------------
// C[M,1024] = (Ah+Al) * (Bh+Bl)^T ; A [M,K] row-major bf16 halves, B [N,K] rows.
// CTA tile 128x128, BK=32, 8 warps, warp tile 64x32. 3-pass split accumulate.
#define HM_SMEM 65536
enum { TEPI_NONE = 0, TEPI_SILU, TEPI_GATE };

template<int EPI>
__device__ __forceinline__ float tepi(float a, int col, const float* __restrict__ vec) {
    if (EPI == TEPI_SILU) return a / (1.f + __expf(-a));
    if (EPI == TEPI_GATE) return 1.f / (1.f + __expf(-(a + vec[col])));
    return a;
}

template<int EPI>
__global__ void __launch_bounds__(256, 1) hmma_gemm(
    const __nv_bfloat16* __restrict__ Ah, const __nv_bfloat16* __restrict__ Al,
    const __nv_bfloat16* __restrict__ Bh, const __nv_bfloat16* __restrict__ Bl,
    float* __restrict__ C, const float* __restrict__ vec)
{
    extern __shared__ __align__(128) char sm[];
    const uint32_t sb = smem_u32(sm);
    const int tid = threadIdx.x, lane = tid & 31, wid = tid >> 5;
    const int m0 = blockIdx.y * 128, n0 = blockIdx.x * 128;
    const int wm = (wid & 1) * 64;         // warp row offset in tile
    const int wn = (wid >> 1) * 32;        // warp col offset in tile

    // stage s at s*32768: Ah +0, Al +8192, Bh +16384, Bl +24576
    // tile layout: row-major, 64B per row (32 bf16), 16B chunks XOR-swizzled
    const int ldrow = (tid >> 2) ;         // 0..63 (2 rows per thread: +0,+64)
    const int ldk16 = tid & 3;

    float acc[4][4][4];
    #pragma unroll
    for (int a = 0; a < 4; a++)
        #pragma unroll
        for (int b = 0; b < 4; b++)
            #pragma unroll
            for (int c = 0; c < 4; c++) acc[a][b][c] = 0.f;

    auto load_chunk = [&](int c) {
        const uint32_t base = sb + (uint32_t)(c & 1) * 32768;
        const int kc = c * 32;
        #pragma unroll
        for (int h = 0; h < 2; h++) {
            int row = ldrow + h * 64;
            uint32_t sw = (uint32_t)row * 64 + (uint32_t)((ldk16 ^ ((row >> 1) & 3)) << 4);
            size_t ga = (size_t)(m0 + row) * 1024 + kc + ldk16 * 8;
            size_t gb = (size_t)(n0 + row) * 1024 + kc + ldk16 * 8;
            cp16(base +         sw, Ah + ga);
            cp16(base +  8192 + sw, Al + ga);
            cp16(base + 16384 + sw, Bh + gb);
            cp16(base + 24576 + sw, Bl + gb);
        }
        CP_COMMIT();
    };

    load_chunk(0);

    const int rowl = lane & 15;
    const int s3 = (rowl >> 1) & 3;
    const int chnk = lane >> 4;

    for (int c = 0; c < 32; c++) {
        if (c + 1 < 32) { load_chunk(c + 1); CP_WAIT(1); }
        else            { CP_WAIT(0); }
        __syncthreads();

        const uint32_t st = sb + (uint32_t)(c & 1) * 32768;
        const uint32_t aBase = st + (uint32_t)(wm + rowl) * 64;
        const uint32_t bBase = st + 16384 + (uint32_t)(wn + rowl) * 64;

        #pragma unroll
        for (int ks = 0; ks < 2; ks++) {
            const uint32_t sw = (uint32_t)(((2 * ks + chnk) ^ s3) << 4);
            uint32_t ah[4][4], al[4][4], bh[2][4], bl[2][4];
            #pragma unroll
            for (int mi = 0; mi < 4; mi++) {
                LDSM4(ah[mi][0], ah[mi][1], ah[mi][2], ah[mi][3], aBase + mi * 1024 + sw);
                LDSM4(al[mi][0], al[mi][1], al[mi][2], al[mi][3], aBase + 8192 + mi * 1024 + sw);
            }
            #pragma unroll
            for (int nf = 0; nf < 2; nf++) {
                LDSM4(bh[nf][0], bh[nf][1], bh[nf][2], bh[nf][3], bBase + nf * 1024 + sw);
                LDSM4(bl[nf][0], bl[nf][1], bl[nf][2], bl[nf][3], bBase + 8192 + nf * 1024 + sw);
            }
            #pragma unroll
            for (int mi = 0; mi < 4; mi++) {
                #pragma unroll
                for (int nj = 0; nj < 4; nj++) {
                    uint32_t b0h = bh[nj >> 1][nj & 1], b1h = bh[nj >> 1][(nj & 1) + 2];
                    uint32_t b0l = bl[nj >> 1][nj & 1], b1l = bl[nj >> 1][(nj & 1) + 2];
                    MMA_BF16(acc[mi][nj], ah[mi], b0h, b1h);
                    MMA_BF16(acc[mi][nj], ah[mi], b0l, b1l);
                    MMA_BF16(acc[mi][nj], al[mi], b0h, b1h);
                }
            }
        }
        __syncthreads();
    }

    // epilogue: frag (mi,nj): rows m0+wm+mi*16+(lane>>2) (+8), cols n0+wn+nj*8+(lane&3)*2
    const int er = lane >> 2, ec = (lane & 3) * 2;
    #pragma unroll
    for (int mi = 0; mi < 4; mi++) {
        #pragma unroll
        for (int nj = 0; nj < 4; nj++) {
            int row = m0 + wm + mi * 16 + er;
            int col = n0 + wn + nj * 8 + ec;
            float2 o0, o1;
            o0.x = tepi<EPI>(acc[mi][nj][0], col,     vec);
            o0.y = tepi<EPI>(acc[mi][nj][1], col + 1, vec);
            o1.x = tepi<EPI>(acc[mi][nj][2], col,     vec);
            o1.y = tepi<EPI>(acc[mi][nj][3], col + 1, vec);
            *(float2*)&C[(size_t)row * 1024 + col]       = o0;
            *(float2*)&C[(size_t)(row + 8) * 1024 + col] = o1;
        }
    }
}

// ---------------- scalar SGEMM (FFMA2) for small GEMMs -------------------------
#define BMt 128
#define BNt 128
#define BKt 16
enum { EPI_NONE = 0, EPI_TANH, EPI_DECAY };

template<int EPI>
__device__ __forceinline__ float epi_apply(float acc, int col,
                                           const float* __restrict__ vec)
{
    if (EPI == EPI_TANH)  return tanhf(acc);
    if (EPI == EPI_DECAY) return __expf(-__expf(vec[col] + acc));
    return acc;
}

template<int EPI>
__global__ void __launch_bounds__(256, 2) sgemm(
    const float* __restrict__ A, int lda,
    const float* __restrict__ Bm, int ldb,
    float* __restrict__ C, int ldc,
    int N, int Kd,
    const float* __restrict__ vec)
{
    __shared__ float As[BKt][BMt];
    __shared__ float Bs[BKt][BNt];

    int tid = threadIdx.x;
    int m0  = blockIdx.y * BMt;
    int n0  = blockIdx.x * BNt;

    int a_row = tid >> 2;
    int a_col = (tid & 3) << 2;
    int b_row = tid >> 5;
    int b_col = (tid & 31) << 2;
    int ty = tid >> 4, tx = tid & 15;

    const float* Aptr = A + (size_t)m0 * lda;
    bool bvalid = (n0 + b_col) < N;
    const float4 z4 = make_float4(0.f, 0.f, 0.f, 0.f);

    float4 a_reg[2], b_reg[2];
    a_reg[0] = *(const float4*)(Aptr + (size_t)a_row       * lda + a_col);
    a_reg[1] = *(const float4*)(Aptr + (size_t)(a_row + 64) * lda + a_col);
    b_reg[0] = bvalid ? *(const float4*)(Bm + (size_t)b_row       * ldb + n0 + b_col) : z4;
    b_reg[1] = bvalid ? *(const float4*)(Bm + (size_t)(b_row + 8) * ldb + n0 + b_col) : z4;

    #pragma unroll
    for (int jj = 0; jj < 4; jj++) {
        As[a_col + jj][a_row]      = ((const float*)&a_reg[0])[jj];
        As[a_col + jj][a_row + 64] = ((const float*)&a_reg[1])[jj];
    }
    *(float4*)&Bs[b_row][b_col]     = b_reg[0];
    *(float4*)&Bs[b_row + 8][b_col] = b_reg[1];
    __syncthreads();

    unsigned long long acc2[8][4];
    #pragma unroll
    for (int i = 0; i < 8; i++)
        #pragma unroll
        for (int j = 0; j < 4; j++)
            acc2[i][j] = 0ull;

    for (int k0 = 0;;) {
        int knext = k0 + BKt;
        if (knext < Kd) {
            a_reg[0] = *(const float4*)(Aptr + (size_t)a_row       * lda + knext + a_col);
            a_reg[1] = *(const float4*)(Aptr + (size_t)(a_row + 64) * lda + knext + a_col);
            b_reg[0] = bvalid ? *(const float4*)(Bm + (size_t)(knext + b_row)     * ldb + n0 + b_col) : z4;
            b_reg[1] = bvalid ? *(const float4*)(Bm + (size_t)(knext + b_row + 8) * ldb + n0 + b_col) : z4;
        }
        #pragma unroll
        for (int kk = 0; kk < BKt; kk++) {
            float a_f[8], b_f[8];
            *(float4*)&a_f[0] = *(const float4*)&As[kk][ty * 8];
            *(float4*)&a_f[4] = *(const float4*)&As[kk][ty * 8 + 4];
            *(float4*)&b_f[0] = *(const float4*)&Bs[kk][tx * 8];
            *(float4*)&b_f[4] = *(const float4*)&Bs[kk][tx * 8 + 4];
            unsigned long long b2[4];
            #pragma unroll
            for (int j = 0; j < 4; j++) b2[j] = pk2(b_f[2*j], b_f[2*j+1]);
            #pragma unroll
            for (int i = 0; i < 8; i++) {
                unsigned long long a2 = pk2(a_f[i], a_f[i]);
                #pragma unroll
                for (int j = 0; j < 4; j++) fma2(acc2[i][j], a2, b2[j]);
            }
        }
        if (knext >= Kd) break;
        __syncthreads();
        #pragma unroll
        for (int jj = 0; jj < 4; jj++) {
            As[a_col + jj][a_row]      = ((const float*)&a_reg[0])[jj];
            As[a_col + jj][a_row + 64] = ((const float*)&a_reg[1])[jj];
        }
        *(float4*)&Bs[b_row][b_col]     = b_reg[0];
        *(float4*)&Bs[b_row + 8][b_col] = b_reg[1];
        __syncthreads();
        k0 = knext;
    }

    float acc[8][8];
    #pragma unroll
    for (int i = 0; i < 8; i++)
        #pragma unroll
        for (int j = 0; j < 4; j++)
            unpk2(acc2[i][j], acc[i][2*j], acc[i][2*j+1]);

    #pragma unroll
    for (int i = 0; i < 8; i++) {
        int row = m0 + ty * 8 + i;
        #pragma unroll
        for (int j = 0; j < 8; j += 4) {
            int col = n0 + tx * 8 + j;
            if (col < N) {
                float4 o;
                o.x = epi_apply<EPI>(acc[i][j + 0], col + 0, vec);
                o.y = epi_apply<EPI>(acc[i][j + 1], col + 1, vec);
                o.z = epi_apply<EPI>(acc[i][j + 2], col + 2, vec);
                o.w = epi_apply<EPI>(acc[i][j + 3], col + 3, vec);
                *(float4*)&C[(size_t)row * ldc + col] = o;
            }
        }
    }
}

// ---------------- fused 5-way token-mix kernel ---------------------------------
__global__ void __launch_bounds__(256) mix5_kernel(
    const float* __restrict__ maa_w2,
    const float* __restrict__ x,
    const float* __restrict__ mw, const float* __restrict__ mk,
    const float* __restrict__ mv, const float* __restrict__ mr,
    const float* __restrict__ mg)
{
    __shared__ float t5s[64][160];
    __shared__ float Bs[32][128];

    int m0 = blockIdx.y * 64;
    int n0 = blockIdx.x * 128;
    int tid = threadIdx.x;

    for (int i = tid; i < 64 * 40; i += 256) {
        int r = i / 40, c4 = (i % 40) * 4;
        *(float4*)&t5s[r][c4] = *(const float4*)&g_t5[(size_t)(m0 + r) * 160 + c4];
    }

    int colg = (tid & 31) * 4;
    int row0 = (tid >> 5) * 8;

    const float* maas[5] = { mw, mk, mv, mr, mg };
    __nv_bfloat16* outH[5] = { nullptr, g_xkh, g_xvh, g_xrh, g_xgh };
    __nv_bfloat16* outL[5] = { nullptr, g_xkl, g_xvl, g_xrl, g_xgl };

    #pragma unroll
    for (int f = 0; f < 5; f++) {
        __syncthreads();
        for (int i = tid; i < 32 * 32; i += 256) {
            int k = i / 32, c4 = (i % 32) * 4;
            *(float4*)&Bs[k][c4] =
                *(const float4*)&maa_w2[((size_t)f * 32 + k) * Dq + n0 + c4];
        }
        __syncthreads();

        float acc0[8], acc1[8], acc2_[8], acc3[8];
        #pragma unroll
        for (int r = 0; r < 8; r++) { acc0[r]=0.f; acc1[r]=0.f; acc2_[r]=0.f; acc3[r]=0.f; }

        #pragma unroll 4
        for (int k = 0; k < 32; k++) {
            float4 b4 = *(const float4*)&Bs[k][colg];
            #pragma unroll
            for (int r = 0; r < 8; r++) {
                float a = t5s[row0 + r][f * 32 + k];
                acc0[r] = fmaf(a, b4.x, acc0[r]);
                acc1[r] = fmaf(a, b4.y, acc1[r]);
                acc2_[r] = fmaf(a, b4.z, acc2_[r]);
                acc3[r] = fmaf(a, b4.w, acc3[r]);
            }
        }

        float4 mva = *(const float4*)&maas[f][n0 + colg];
        #pragma unroll
        for (int r = 0; r < 8; r++) {
            size_t idx = (size_t)(m0 + row0 + r) * Dq + n0 + colg;
            float4 xv4 = *(const float4*)&x[idx];
            float4 dx4 = *(const float4*)&g_dx[idx];
            float4 o;
            o.x = xv4.x + dx4.x * (mva.x + acc0[r]);
            o.y = xv4.y + dx4.y * (mva.y + acc1[r]);
            o.z = xv4.z + dx4.z * (mva.z + acc2_[r]);
            o.w = xv4.w + dx4.w * (mva.w + acc3[r]);
            if (f == 0) *(float4*)&g_xw[idx] = o;
            else        store_split4(outH[f], outL[f], idx, o);
        }
    }
}

// ---------------- bidirectional WKV recurrence ---------------------------------
__global__ void __launch_bounds__(64) wkv_kernel()
{
    int bh  = blockIdx.x;
    int dir = blockIdx.y;
    int b = bh / Hq, h = bh % Hq;
    size_t base = (size_t)b * Tq * Dq + (size_t)h * Kq;
    int j = threadIdx.x;

    __shared__ float s_r[2][Kq], s_k[2][Kq], s_w[2][Kq];

    float S[Kq];
    #pragma unroll
    for (int i = 0; i < Kq; i++) S[i] = 0.f;

    if (dir == 0) {
        for (int t = 0; t < Tq; t++) {
            size_t off = base + (size_t)t * Dq;
            int buf = t & 1;
            s_r[buf][j] = g_r[off + j];
            s_k[buf][j] = g_k[off + j];
            s_w[buf][j] = g_ww[off + j];
            __syncthreads();
            float vj = g_v[off + j];
            float y0 = 0.f, y1 = 0.f, y2 = 0.f, y3 = 0.f;
            const float4* r4 = (const float4*)s_r[buf];
            const float4* k4 = (const float4*)s_k[buf];
            const float4* w4 = (const float4*)s_w[buf];
            #pragma unroll
            for (int i4 = 0; i4 < Kq / 4; i4++) {
                float4 rv = r4[i4], kv = k4[i4], wv = w4[i4];
                float* Sp = &S[i4 * 4];
                Sp[0] = fmaf(wv.x, Sp[0], kv.x * vj); y0 = fmaf(rv.x, Sp[0], y0);
                Sp[1] = fmaf(wv.y, Sp[1], kv.y * vj); y1 = fmaf(rv.y, Sp[1], y1);
                Sp[2] = fmaf(wv.z, Sp[2], kv.z * vj); y2 = fmaf(rv.z, Sp[2], y2);
                Sp[3] = fmaf(wv.w, Sp[3], kv.w * vj); y3 = fmaf(rv.w, Sp[3], y3);
            }
            g_yf[off + j] = (y0 + y1) + (y2 + y3);
        }
    } else {
        for (int tt = 0; tt < Tq; tt++) {
            int t = Tq - 1 - tt;
            size_t off = base + (size_t)t * Dq;
            int buf = tt & 1;
            s_r[buf][j] = g_r[off + j];
            s_k[buf][j] = g_k[off + j];
            s_w[buf][j] = g_ww[off + j];
            __syncthreads();
            float vj = g_v[off + j];
            float y0 = 0.f, y1 = 0.f, y2 = 0.f, y3 = 0.f;
            const float4* r4 = (const float4*)s_r[buf];
            const float4* k4 = (const float4*)s_k[buf];
            const float4* w4 = (const float4*)s_w[buf];
            #pragma unroll
            for (int i4 = 0; i4 < Kq / 4; i4++) {
                float4 rv = r4[i4], kv = k4[i4], wv = w4[i4];
                float* Sp = &S[i4 * 4];
                y0 = fmaf(rv.x, Sp[0], y0); Sp[0] = wv.x * fmaf(kv.x, vj, Sp[0]);
                y1 = fmaf(rv.y, Sp[1], y1); Sp[1] = wv.y * fmaf(kv.y, vj, Sp[1]);
                y2 = fmaf(rv.z, Sp[2], y2); Sp[2] = wv.z * fmaf(kv.z, vj, Sp[2]);
                y3 = fmaf(rv.w, Sp[3], y3); Sp[3] = wv.w * fmaf(kv.w, vj, Sp[3]);
            }
            g_yb[off + j] = (y0 + y1) + (y2 + y3);
        }
    }
}

// ---------------- groupnorm + output gate + silu-gate (→ z hi/lo) ---------------
__global__ void __launch_bounds__(128) gn_kernel(const float* __restrict__ ln_w,
                                                 const float* __restrict__ ln_b)
{
    int gidx = blockIdx.x * 4 + (threadIdx.x >> 5);
    int lane = threadIdx.x & 31;
    int bt = gidx / Hq, h = gidx % Hq;
    size_t rowbase = (size_t)bt * Dq + (size_t)h * Kq;
    size_t i0 = rowbase + lane, i1 = rowbase + lane + 32;

    float a = (g_yf[i0] + g_yb[i0]) * g_gate[i0];
    float c = (g_yf[i1] + g_yb[i1]) * g_gate[i1];
    float s = a + c, sq = a * a + c * c;
    #pragma unroll
    for (int o = 16; o; o >>= 1) {
        s  += __shfl_xor_sync(0xffffffffu, s,  o);
        sq += __shfl_xor_sync(0xffffffffu, sq, o);
    }
    float mean = s * (1.f / 64.f);
    float var  = sq * (1.f / 64.f) - mean * mean;
    float rstd = rsqrtf(var + 6.4e-4f);
    int d0 = h * Kq + lane, d1 = d0 + 32;
    float z0 = ((a - mean) * rstd * ln_w[d0] + ln_b[d0]) * g_g[i0];
    float z1 = ((c - mean) * rstd * ln_w[d1] + ln_b[d1]) * g_g[i1];
    __nv_bfloat16 h0 = __float2bfloat16(z0);
    __nv_bfloat16 h1 = __float2bfloat16(z1);
    g_zh[i0] = h0; g_zl[i0] = __float2bfloat16(z0 - __bfloat162float(h0));
    g_zh[i1] = h1; g_zl[i1] = __float2bfloat16(z1 - __bfloat162float(h1));
}

// ---------------- launch --------------------------------------------------------
extern "C" void kernel_launch(void* const* d_in, const int* in_sizes, int n_in,
                              void* d_out, int out_size)
{
    const float* x          = (const float*)d_in[0];
    const float* conv_w     = (const float*)d_in[1];
    const float* maa_x      = (const float*)d_in[2];
    const float* maa_w      = (const float*)d_in[3];
    const float* maa_k      = (const float*)d_in[4];
    const float* maa_v      = (const float*)d_in[5];
    const float* maa_r      = (const float*)d_in[6];
    const float* maa_g      = (const float*)d_in[7];
    const float* maa_w1     = (const float*)d_in[8];
    const float* maa_w2     = (const float*)d_in[9];
    const float* time_decay = (const float*)d_in[10];
    const float* decay_w1   = (const float*)d_in[11];
    const float* decay_w2   = (const float*)d_in[12];
    const float* Wr         = (const float*)d_in[13];
    const float* Wk         = (const float*)d_in[14];
    const float* Wv         = (const float*)d_in[15];
    const float* Wg         = (const float*)d_in[16];
    const float* Wo         = (const float*)d_in[17];
    const float* ln_w       = (const float*)d_in[18];
    const float* ln_b       = (const float*)d_in[19];
    const float* gate_w     = (const float*)d_in[20];
    const float* gate_b     = (const float*)d_in[21];
    float* out = (float*)d_out;

    float *p_xxx, *p_t5, *p_xw, *p_r, *p_k, *p_v, *p_g, *p_h, *p_ww, *p_gate;
    __nv_bfloat16 *p_dxh, *p_dxl, *p_xkh, *p_xkl, *p_xvh, *p_xvl;
    __nv_bfloat16 *p_xrh, *p_xrl, *p_xgh, *p_xgl, *p_zh, *p_zl, *p_wh, *p_wl;
    cudaGetSymbolAddress((void**)&p_xxx,  g_xxx);
    cudaGetSymbolAddress((void**)&p_t5,   g_t5);
    cudaGetSymbolAddress((void**)&p_xw,   g_xw);
    cudaGetSymbolAddress((void**)&p_r,    g_r);
    cudaGetSymbolAddress((void**)&p_k,    g_k);
    cudaGetSymbolAddress((void**)&p_v,    g_v);
    cudaGetSymbolAddress((void**)&p_g,    g_g);
    cudaGetSymbolAddress((void**)&p_h,    g_hbuf);
    cudaGetSymbolAddress((void**)&p_ww,   g_ww);
    cudaGetSymbolAddress((void**)&p_gate, g_gate);
    cudaGetSymbolAddress((void**)&p_dxh,  g_dxh);
    cudaGetSymbolAddress((void**)&p_dxl,  g_dxl);
    cudaGetSymbolAddress((void**)&p_xkh,  g_xkh);
    cudaGetSymbolAddress((void**)&p_xkl,  g_xkl);
    cudaGetSymbolAddress((void**)&p_xvh,  g_xvh);
    cudaGetSymbolAddress((void**)&p_xvl,  g_xvl);
    cudaGetSymbolAddress((void**)&p_xrh,  g_xrh);
    cudaGetSymbolAddress((void**)&p_xrl,  g_xrl);
    cudaGetSymbolAddress((void**)&p_xgh,  g_xgh);
    cudaGetSymbolAddress((void**)&p_xgl,  g_xgl);
    cudaGetSymbolAddress((void**)&p_zh,   g_zh);
    cudaGetSymbolAddress((void**)&p_zl,   g_zl);
    cudaGetSymbolAddress((void**)&p_wh,   g_wh);
    cudaGetSymbolAddress((void**)&p_wl,   g_wl);

    cudaFuncSetAttribute(hmma_gemm<TEPI_NONE>, cudaFuncAttributeMaxDynamicSharedMemorySize, HM_SMEM);
    cudaFuncSetAttribute(hmma_gemm<TEPI_SILU>, cudaFuncAttributeMaxDynamicSharedMemorySize, HM_SMEM);
    cudaFuncSetAttribute(hmma_gemm<TEPI_GATE>, cudaFuncAttributeMaxDynamicSharedMemorySize, HM_SMEM);

    // 0) conv / dx(+hi/lo) / xxx
    {
        int threads = 256;
        int blocks  = (int)((BTDq + threads - 1) / threads);
        conv_kernel<<<blocks, threads>>>(x, conv_w, maa_x);
    }

    // 1) weight transpose + split (slots: Wr,Wk,Wv,Wg,gate_w,Wo)
    {
        dim3 g(32, 32, 6);
        wsplit_kernel<<<g, 256>>>(Wr, Wk, Wv, Wg, gate_w, Wo);
    }

    dim3 blk(256);
    dim3 grid_t5(2, Mq / BMt);
    dim3 grid_64(1, Mq / BMt);
    dim3 grid_dec(Dq / BNt, Mq / BMt);
    dim3 hm_grid(8, Mq / 128);   // N/128 x M/128

    // 2) t5 = tanh(xxx @ maa_w1)
    sgemm<EPI_TANH><<<grid_t5, blk>>>(p_xxx, Dq, maa_w1, 160, p_t5, 160,
                                      160, Dq, nullptr);

    // 3) fused token-mix: xw fp32; xk/xv/xr/xg as bf16 hi/lo
    {
        dim3 g(Dq / 128, Mq / 64);
        mix5_kernel<<<g, 256>>>(maa_w2, x, maa_w, maa_k, maa_v, maa_r, maa_g);
    }

    const size_t WS = 1024 * 1024;
    // 4) big projections on tensor cores (HMMA mma.sync)
    hmma_gemm<TEPI_NONE><<<hm_grid, 256, HM_SMEM>>>(p_xrh, p_xrl, p_wh + 0*WS, p_wl + 0*WS, p_r, nullptr);
    hmma_gemm<TEPI_NONE><<<hm_grid, 256, HM_SMEM>>>(p_xkh, p_xkl, p_wh + 1*WS, p_wl + 1*WS, p_k, nullptr);
    hmma_gemm<TEPI_NONE><<<hm_grid, 256, HM_SMEM>>>(p_xvh, p_xvl, p_wh + 2*WS, p_wl + 2*WS, p_v, nullptr);
    hmma_gemm<TEPI_SILU><<<hm_grid, 256, HM_SMEM>>>(p_xgh, p_xgl, p_wh + 3*WS, p_wl + 3*WS, p_g, nullptr);
    hmma_gemm<TEPI_GATE><<<hm_grid, 256, HM_SMEM>>>(p_dxh, p_dxl, p_wh + 4*WS, p_wl + 4*WS, p_gate, gate_b);

    // 5) decay MLP (scalar)
    sgemm<EPI_TANH><<<grid_64, blk>>>(p_xw, Dq, decay_w1, 64, p_h, 64,
                                      64, Dq, nullptr);
    sgemm<EPI_DECAY><<<grid_dec, blk>>>(p_h, 64, decay_w2, Dq, p_ww, Dq,
                                        Dq, 64, time_decay);

    // 6) bidirectional recurrence
    {
        dim3 g(Bq * Hq, 2);
        wkv_kernel<<<g, 64>>>();
    }

    // 7) gate + groupnorm + silu-gate → z hi/lo
    gn_kernel<<<(Mq * Hq) / 4, 128>>>(ln_w, ln_b);

    // 8) out = z @ Wo (HMMA)
    hmma_gemm<TEPI_NONE><<<hm_grid, 256, HM_SMEM>>>(p_zh, p_zl, p_wh + 5*WS, p_wl + 5*WS, out, nullptr);
}

// round 5
// speedup vs baseline: 2.5364x; 1.5220x over previous
#include <cuda_runtime.h>
#include <cuda_bf16.h>
#include <math.h>
#include <stdint.h>

// Problem constants
#define Bq 8
#define Tq 2048
#define Dq 1024
#define Hq 16
#define Kq 64
#define Mq (Bq*Tq)                 // 16384 rows
#define BTDq ((size_t)Mq*(size_t)Dq)

// ---------------- scratch (device globals; no allocations allowed) -------------
__device__ float g_xxx [Mq*Dq];
__device__ float g_t5  [Mq*160];
__device__ float g_xw  [Mq*Dq];
__device__ float g_r   [Mq*Dq];
__device__ float g_k   [Mq*Dq];
__device__ float g_v   [Mq*Dq];
__device__ float g_g   [Mq*Dq];
__device__ float g_hbuf[Mq*64];
__device__ float g_ww  [Mq*Dq];
__device__ float g_gate[Mq*Dq];
__device__ float g_yf  [Mq*Dq];
__device__ float g_yb  [Mq*Dq];

// bf16 hi/lo split activations
__device__ __nv_bfloat16 g_dxh[Mq*Dq], g_dxl[Mq*Dq];
__device__ __nv_bfloat16 g_xkh[Mq*Dq], g_xkl[Mq*Dq];
__device__ __nv_bfloat16 g_xvh[Mq*Dq], g_xvl[Mq*Dq];
__device__ __nv_bfloat16 g_xrh[Mq*Dq], g_xrl[Mq*Dq];
__device__ __nv_bfloat16 g_xgh[Mq*Dq], g_xgl[Mq*Dq];
__device__ __nv_bfloat16 g_zh [Mq*Dq], g_zl [Mq*Dq];
// transposed weights [N,K] hi/lo, 6 slots: Wr,Wk,Wv,Wg,gate_w,Wo
__device__ __nv_bfloat16 g_wh[6*1024*1024], g_wl[6*1024*1024];

// ---------------- helpers -------------------------------------------------------
__device__ __forceinline__ uint32_t smem_u32(const void* p) {
    uint32_t a;
    asm("{ .reg .u64 t; cvta.to.shared.u64 t, %1; cvt.u32.u64 %0, t; }" : "=r"(a) : "l"(p));
    return a;
}
__device__ __forceinline__ void cp16(uint32_t dst, const void* src) {
    asm volatile("cp.async.cg.shared.global [%0], [%1], 16;" :: "r"(dst), "l"(src));
}
__device__ __forceinline__ void cp4(uint32_t dst, const void* src) {
    asm volatile("cp.async.ca.shared.global [%0], [%1], 4;" :: "r"(dst), "l"(src));
}
#define CP_COMMIT() asm volatile("cp.async.commit_group;" ::: "memory")
#define CP_WAIT(n)  asm volatile("cp.async.wait_group %0;" :: "n"(n) : "memory")

#define LDSM4(R0, R1, R2, R3, ADDR) \
    asm volatile("ldmatrix.sync.aligned.m8n8.x4.shared.b16 {%0,%1,%2,%3}, [%4];" \
        : "=r"(R0), "=r"(R1), "=r"(R2), "=r"(R3) : "r"(ADDR))

#define MMA_BF16(D, A, B0, B1) \
    asm volatile("mma.sync.aligned.m16n8k16.row.col.f32.bf16.bf16.f32 " \
        "{%0,%1,%2,%3}, {%4,%5,%6,%7}, {%8,%9}, {%0,%1,%2,%3};" \
        : "+f"((D)[0]), "+f"((D)[1]), "+f"((D)[2]), "+f"((D)[3]) \
        : "r"((A)[0]), "r"((A)[1]), "r"((A)[2]), "r"((A)[3]), "r"(B0), "r"(B1))

// packed f32x2 helpers
__device__ __forceinline__ unsigned long long pk2(float lo, float hi) {
    unsigned long long r;
    asm("mov.b64 %0, {%1, %2};" : "=l"(r) : "f"(lo), "f"(hi));
    return r;
}
__device__ __forceinline__ void fma2(unsigned long long& d,
                                     unsigned long long a,
                                     unsigned long long b) {
    asm("fma.rn.f32x2 %0, %1, %2, %0;" : "+l"(d) : "l"(a), "l"(b));
}
__device__ __forceinline__ unsigned long long fma2v(unsigned long long a,
                                                    unsigned long long b,
                                                    unsigned long long c) {
    unsigned long long d;
    asm("fma.rn.f32x2 %0, %1, %2, %3;" : "=l"(d) : "l"(a), "l"(b), "l"(c));
    return d;
}
__device__ __forceinline__ unsigned long long mul2(unsigned long long a,
                                                   unsigned long long b) {
    unsigned long long d;
    asm("mul.rn.f32x2 %0, %1, %2;" : "=l"(d) : "l"(a), "l"(b));
    return d;
}
__device__ __forceinline__ void unpk2(unsigned long long v, float& lo, float& hi) {
    asm("mov.b64 {%0, %1}, %2;" : "=f"(lo), "=f"(hi) : "l"(v));
}

// hi/lo split store of 4 consecutive floats
__device__ __forceinline__ void store_split4(__nv_bfloat16* H, __nv_bfloat16* L,
                                             size_t idx, float4 o) {
    __nv_bfloat162 h01 = __floats2bfloat162_rn(o.x, o.y);
    __nv_bfloat162 h23 = __floats2bfloat162_rn(o.z, o.w);
    float2 f01 = __bfloat1622float2(h01);
    float2 f23 = __bfloat1622float2(h23);
    __nv_bfloat162 l01 = __floats2bfloat162_rn(o.x - f01.x, o.y - f01.y);
    __nv_bfloat162 l23 = __floats2bfloat162_rn(o.z - f23.x, o.w - f23.y);
    uint2 hv = make_uint2(*(unsigned*)&h01, *(unsigned*)&h23);
    uint2 lv = make_uint2(*(unsigned*)&l01, *(unsigned*)&l23);
    *(uint2*)&H[idx] = hv;
    *(uint2*)&L[idx] = lv;
}
// hi/lo reconstruction of 4 consecutive floats
__device__ __forceinline__ float4 load_split4(const __nv_bfloat16* __restrict__ H,
                                              const __nv_bfloat16* __restrict__ L,
                                              size_t idx) {
    uint2 hv = *(const uint2*)&H[idx];
    uint2 lv = *(const uint2*)&L[idx];
    float2 h01 = __bfloat1622float2(*(__nv_bfloat162*)&hv.x);
    float2 h23 = __bfloat1622float2(*(__nv_bfloat162*)&hv.y);
    float2 l01 = __bfloat1622float2(*(__nv_bfloat162*)&lv.x);
    float2 l23 = __bfloat1622float2(*(__nv_bfloat162*)&lv.y);
    return make_float4(h01.x + l01.x, h01.y + l01.y, h23.x + l23.x, h23.y + l23.y);
}

// ---------------- kernel: depthwise conv (k=3), dx hi/lo, xxx ------------------
__global__ void conv_kernel(const float* __restrict__ x,
                            const float* __restrict__ cw,
                            const float* __restrict__ maa_x)
{
    size_t idx = (size_t)blockIdx.x * blockDim.x + threadIdx.x;
    if (idx >= BTDq) return;
    int d = (int)(idx & (Dq - 1));
    int t = (int)((idx / Dq) & (Tq - 1));
    float x0 = x[idx];
    float xm = (t > 0)      ? x[idx - Dq] : 0.f;
    float xp = (t < Tq - 1) ? x[idx + Dq] : 0.f;
    float dxv = cw[d*3+0]*xm + cw[d*3+1]*x0 + cw[d*3+2]*xp - x0;
    g_xxx[idx] = x0 + dxv * maa_x[d];
    __nv_bfloat16 h = __float2bfloat16(dxv);
    g_dxh[idx] = h;
    g_dxl[idx] = __float2bfloat16(dxv - __bfloat162float(h));
}

// ---------------- kernel: weight transpose + bf16 split ------------------------
__global__ void __launch_bounds__(256) wsplit_kernel(
    const float* __restrict__ W0, const float* __restrict__ W1,
    const float* __restrict__ W2, const float* __restrict__ W3,
    const float* __restrict__ W4, const float* __restrict__ W5)
{
    __shared__ float tile[32][33];
    const float* Ws[6] = { W0, W1, W2, W3, W4, W5 };
    const float* W = Ws[blockIdx.z];
    __nv_bfloat16* H = g_wh + (size_t)blockIdx.z * 1024 * 1024;
    __nv_bfloat16* L = g_wl + (size_t)blockIdx.z * 1024 * 1024;
    int n0 = blockIdx.x * 32, k0 = blockIdx.y * 32;
    int tx = threadIdx.x & 31, ty = threadIdx.x >> 5;  // 32 x 8
    #pragma unroll
    for (int i = 0; i < 4; i++)
        tile[ty + i*8][tx] = W[(size_t)(k0 + ty + i*8) * 1024 + n0 + tx];
    __syncthreads();
    #pragma unroll
    for (int i = 0; i < 4; i++) {
        float v = tile[tx][ty + i*8];
        __nv_bfloat16 h = __float2bfloat16(v);
        size_t o = (size_t)(n0 + ty + i*8) * 1024 + k0 + tx;
        H[o] = h;
        L[o] = __float2bfloat16(v - __bfloat162float(h));
    }
}

// ---------------- HMMA bf16 split GEMM (mma.sync), 3-stage pipeline ------------
#define HM_SMEM 98304
enum { TEPI_NONE = 0, TEPI_SILU, TEPI_GATE };

template<int EPI>
__device__ __forceinline__ float tepi(float a, int col, const float* __restrict__ vec) {
    if (EPI == TEPI_SILU) return a / (1.f + __expf(-a));
    if (EPI == TEPI_GATE) return 1.f / (1.f + __expf(-(a + vec[col])));
    return a;
}

template<int EPI>
__global__ void __launch_bounds__(256, 1) hmma_gemm(
    const __nv_bfloat16* __restrict__ Ah, const __nv_bfloat16* __restrict__ Al,
    const __nv_bfloat16* __restrict__ Bh, const __nv_bfloat16* __restrict__ Bl,
    float* __restrict__ C, const float* __restrict__ vec)
{
    extern __shared__ __align__(128) char sm[];
    const uint32_t sb = smem_u32(sm);
    const int tid = threadIdx.x, lane = tid & 31, wid = tid >> 5;
    const int m0 = blockIdx.y * 128, n0 = blockIdx.x * 128;
    const int wm = (wid & 1) * 64;
    const int wn = (wid >> 1) * 32;

    const int ldrow = (tid >> 2);
    const int ldk16 = tid & 3;

    float acc[4][4][4];
    #pragma unroll
    for (int a = 0; a < 4; a++)
        #pragma unroll
        for (int b = 0; b < 4; b++)
            #pragma unroll
            for (int c = 0; c < 4; c++) acc[a][b][c] = 0.f;

    auto load_chunk = [&](int c) {
        const uint32_t base = sb + (uint32_t)(c % 3) * 32768;
        const int kc = c * 32;
        #pragma unroll
        for (int h = 0; h < 2; h++) {
            int row = ldrow + h * 64;
            uint32_t sw = (uint32_t)row * 64 + (uint32_t)((ldk16 ^ ((row >> 1) & 3)) << 4);
            size_t ga = (size_t)(m0 + row) * 1024 + kc + ldk16 * 8;
            size_t gb = (size_t)(n0 + row) * 1024 + kc + ldk16 * 8;
            cp16(base +         sw, Ah + ga);
            cp16(base +  8192 + sw, Al + ga);
            cp16(base + 16384 + sw, Bh + gb);
            cp16(base + 24576 + sw, Bl + gb);
        }
        CP_COMMIT();
    };

    load_chunk(0);
    load_chunk(1);

    const int rowl = lane & 15;
    const int s3 = (rowl >> 1) & 3;
    const int chnk = lane >> 4;

    for (int c = 0; c < 32; c++) {
        CP_WAIT(1);
        __syncthreads();
        if (c + 2 < 32) load_chunk(c + 2);

        const uint32_t st = sb + (uint32_t)(c % 3) * 32768;
        const uint32_t aBase = st + (uint32_t)(wm + rowl) * 64;
        const uint32_t bBase = st + 16384 + (uint32_t)(wn + rowl) * 64;

        #pragma unroll
        for (int ks = 0; ks < 2; ks++) {
            const uint32_t sw = (uint32_t)(((2 * ks + chnk) ^ s3) << 4);
            uint32_t ah[4][4], al[4][4], bh[2][4], bl[2][4];
            #pragma unroll
            for (int mi = 0; mi < 4; mi++) {
                LDSM4(ah[mi][0], ah[mi][1], ah[mi][2], ah[mi][3], aBase + mi * 1024 + sw);
                LDSM4(al[mi][0], al[mi][1], al[mi][2], al[mi][3], aBase + 8192 + mi * 1024 + sw);
            }
            #pragma unroll
            for (int nf = 0; nf < 2; nf++) {
                LDSM4(bh[nf][0], bh[nf][1], bh[nf][2], bh[nf][3], bBase + nf * 1024 + sw);
                LDSM4(bl[nf][0], bl[nf][1], bl[nf][2], bl[nf][3], bBase + 8192 + nf * 1024 + sw);
            }
            #pragma unroll
            for (int mi = 0; mi < 4; mi++) {
                #pragma unroll
                for (int nj = 0; nj < 4; nj++) {
                    uint32_t b0h = bh[nj >> 1][nj & 1], b1h = bh[nj >> 1][(nj & 1) + 2];
                    uint32_t b0l = bl[nj >> 1][nj & 1], b1l = bl[nj >> 1][(nj & 1) + 2];
                    MMA_BF16(acc[mi][nj], ah[mi], b0h, b1h);
                    MMA_BF16(acc[mi][nj], ah[mi], b0l, b1l);
                    MMA_BF16(acc[mi][nj], al[mi], b0h, b1h);
                }
            }
        }
    }

    const int er = lane >> 2, ec = (lane & 3) * 2;
    #pragma unroll
    for (int mi = 0; mi < 4; mi++) {
        #pragma unroll
        for (int nj = 0; nj < 4; nj++) {
            int row = m0 + wm + mi * 16 + er;
            int col = n0 + wn + nj * 8 + ec;
            float2 o0, o1;
            o0.x = tepi<EPI>(acc[mi][nj][0], col,     vec);
            o0.y = tepi<EPI>(acc[mi][nj][1], col + 1, vec);
            o1.x = tepi<EPI>(acc[mi][nj][2], col,     vec);
            o1.y = tepi<EPI>(acc[mi][nj][3], col + 1, vec);
            *(float2*)&C[(size_t)row * 1024 + col]       = o0;
            *(float2*)&C[(size_t)(row + 8) * 1024 + col] = o1;
        }
    }
}

// ---------------- scalar SGEMM (FFMA2) for small GEMMs -------------------------
#define BMt 128
#define BNt 128
#define BKt 16
enum { EPI_NONE = 0, EPI_TANH, EPI_DECAY };

template<int EPI>
__device__ __forceinline__ float epi_apply(float acc, int col,
                                           const float* __restrict__ vec)
{
    if (EPI == EPI_TANH)  return tanhf(acc);
    if (EPI == EPI_DECAY) return __expf(-__expf(vec[col] + acc));
    return acc;
}

template<int EPI>
__global__ void __launch_bounds__(256, 2) sgemm(
    const float* __restrict__ A, int lda,
    const float* __restrict__ Bm, int ldb,
    float* __restrict__ C, int ldc,
    int N, int Kd,
    const float* __restrict__ vec)
{
    __shared__ float As[BKt][BMt];
    __shared__ float Bs[BKt][BNt];

    int tid = threadIdx.x;
    int m0  = blockIdx.y * BMt;
    int n0  = blockIdx.x * BNt;

    int a_row = tid >> 2;
    int a_col = (tid & 3) << 2;
    int b_row = tid >> 5;
    int b_col = (tid & 31) << 2;
    int ty = tid >> 4, tx = tid & 15;

    const float* Aptr = A + (size_t)m0 * lda;
    bool bvalid = (n0 + b_col) < N;
    const float4 z4 = make_float4(0.f, 0.f, 0.f, 0.f);

    float4 a_reg[2], b_reg[2];
    a_reg[0] = *(const float4*)(Aptr + (size_t)a_row       * lda + a_col);
    a_reg[1] = *(const float4*)(Aptr + (size_t)(a_row + 64) * lda + a_col);
    b_reg[0] = bvalid ? *(const float4*)(Bm + (size_t)b_row       * ldb + n0 + b_col) : z4;
    b_reg[1] = bvalid ? *(const float4*)(Bm + (size_t)(b_row + 8) * ldb + n0 + b_col) : z4;

    #pragma unroll
    for (int jj = 0; jj < 4; jj++) {
        As[a_col + jj][a_row]      = ((const float*)&a_reg[0])[jj];
        As[a_col + jj][a_row + 64] = ((const float*)&a_reg[1])[jj];
    }
    *(float4*)&Bs[b_row][b_col]     = b_reg[0];
    *(float4*)&Bs[b_row + 8][b_col] = b_reg[1];
    __syncthreads();

    unsigned long long acc2[8][4];
    #pragma unroll
    for (int i = 0; i < 8; i++)
        #pragma unroll
        for (int j = 0; j < 4; j++)
            acc2[i][j] = 0ull;

    for (int k0 = 0;;) {
        int knext = k0 + BKt;
        if (knext < Kd) {
            a_reg[0] = *(const float4*)(Aptr + (size_t)a_row       * lda + knext + a_col);
            a_reg[1] = *(const float4*)(Aptr + (size_t)(a_row + 64) * lda + knext + a_col);
            b_reg[0] = bvalid ? *(const float4*)(Bm + (size_t)(knext + b_row)     * ldb + n0 + b_col) : z4;
            b_reg[1] = bvalid ? *(const float4*)(Bm + (size_t)(knext + b_row + 8) * ldb + n0 + b_col) : z4;
        }
        #pragma unroll
        for (int kk = 0; kk < BKt; kk++) {
            float a_f[8], b_f[8];
            *(float4*)&a_f[0] = *(const float4*)&As[kk][ty * 8];
            *(float4*)&a_f[4] = *(const float4*)&As[kk][ty * 8 + 4];
            *(float4*)&b_f[0] = *(const float4*)&Bs[kk][tx * 8];
            *(float4*)&b_f[4] = *(const float4*)&Bs[kk][tx * 8 + 4];
            unsigned long long b2[4];
            #pragma unroll
            for (int j = 0; j < 4; j++) b2[j] = pk2(b_f[2*j], b_f[2*j+1]);
            #pragma unroll
            for (int i = 0; i < 8; i++) {
                unsigned long long a2 = pk2(a_f[i], a_f[i]);
                #pragma unroll
                for (int j = 0; j < 4; j++) fma2(acc2[i][j], a2, b2[j]);
            }
        }
        if (knext >= Kd) break;
        __syncthreads();
        #pragma unroll
        for (int jj = 0; jj < 4; jj++) {
            As[a_col + jj][a_row]      = ((const float*)&a_reg[0])[jj];
            As[a_col + jj][a_row + 64] = ((const float*)&a_reg[1])[jj];
        }
        *(float4*)&Bs[b_row][b_col]     = b_reg[0];
        *(float4*)&Bs[b_row + 8][b_col] = b_reg[1];
        __syncthreads();
        k0 = knext;
    }

    float acc[8][8];
    #pragma unroll
    for (int i = 0; i < 8; i++)
        #pragma unroll
        for (int j = 0; j < 4; j++)
            unpk2(acc2[i][j], acc[i][2*j], acc[i][2*j+1]);

    #pragma unroll
    for (int i = 0; i < 8; i++) {
        int row = m0 + ty * 8 + i;
        #pragma unroll
        for (int j = 0; j < 8; j += 4) {
            int col = n0 + tx * 8 + j;
            if (col < N) {
                float4 o;
                o.x = epi_apply<EPI>(acc[i][j + 0], col + 0, vec);
                o.y = epi_apply<EPI>(acc[i][j + 1], col + 1, vec);
                o.z = epi_apply<EPI>(acc[i][j + 2], col + 2, vec);
                o.w = epi_apply<EPI>(acc[i][j + 3], col + 3, vec);
                *(float4*)&C[(size_t)row * ldc + col] = o;
            }
        }
    }
}

// ---------------- fused 5-way token-mix kernel ---------------------------------
__global__ void __launch_bounds__(256) mix5_kernel(
    const float* __restrict__ maa_w2,
    const float* __restrict__ x,
    const float* __restrict__ mw, const float* __restrict__ mk,
    const float* __restrict__ mv, const float* __restrict__ mr,
    const float* __restrict__ mg)
{
    __shared__ float t5s[64][160];
    __shared__ float Bs[32][128];

    int m0 = blockIdx.y * 64;
    int n0 = blockIdx.x * 128;
    int tid = threadIdx.x;

    for (int i = tid; i < 64 * 40; i += 256) {
        int r = i / 40, c4 = (i % 40) * 4;
        *(float4*)&t5s[r][c4] = *(const float4*)&g_t5[(size_t)(m0 + r) * 160 + c4];
    }

    int colg = (tid & 31) * 4;
    int row0 = (tid >> 5) * 8;

    const float* maas[5] = { mw, mk, mv, mr, mg };
    __nv_bfloat16* outH[5] = { nullptr, g_xkh, g_xvh, g_xrh, g_xgh };
    __nv_bfloat16* outL[5] = { nullptr, g_xkl, g_xvl, g_xrl, g_xgl };

    #pragma unroll
    for (int f = 0; f < 5; f++) {
        __syncthreads();
        for (int i = tid; i < 32 * 32; i += 256) {
            int k = i / 32, c4 = (i % 32) * 4;
            *(float4*)&Bs[k][c4] =
                *(const float4*)&maa_w2[((size_t)f * 32 + k) * Dq + n0 + c4];
        }
        __syncthreads();

        float acc0[8], acc1[8], acc2_[8], acc3[8];
        #pragma unroll
        for (int r = 0; r < 8; r++) { acc0[r]=0.f; acc1[r]=0.f; acc2_[r]=0.f; acc3[r]=0.f; }

        #pragma unroll 4
        for (int k = 0; k < 32; k++) {
            float4 b4 = *(const float4*)&Bs[k][colg];
            #pragma unroll
            for (int r = 0; r < 8; r++) {
                float a = t5s[row0 + r][f * 32 + k];
                acc0[r] = fmaf(a, b4.x, acc0[r]);
                acc1[r] = fmaf(a, b4.y, acc1[r]);
                acc2_[r] = fmaf(a, b4.z, acc2_[r]);
                acc3[r] = fmaf(a, b4.w, acc3[r]);
            }
        }

        float4 mva = *(const float4*)&maas[f][n0 + colg];
        #pragma unroll
        for (int r = 0; r < 8; r++) {
            size_t idx = (size_t)(m0 + row0 + r) * Dq + n0 + colg;
            float4 xv4 = *(const float4*)&x[idx];
            float4 dx4 = load_split4(g_dxh, g_dxl, idx);
            float4 o;
            o.x = xv4.x + dx4.x * (mva.x + acc0[r]);
            o.y = xv4.y + dx4.y * (mva.y + acc1[r]);
            o.z = xv4.z + dx4.z * (mva.z + acc2_[r]);
            o.w = xv4.w + dx4.w * (mva.w + acc3[r]);
            if (f == 0) *(float4*)&g_xw[idx] = o;
            else        store_split4(outH[f], outL[f], idx, o);
        }
    }
}

// ---------------- bidirectional WKV recurrence (cp.async 4-deep, f32x2) --------
__global__ void __launch_bounds__(64) wkv_kernel()
{
    int bh  = blockIdx.x;
    int dir = blockIdx.y;
    int b = bh / Hq, h = bh % Hq;
    size_t base = (size_t)b * Tq * Dq + (size_t)h * Kq;
    int j = threadIdx.x;

    __shared__ __align__(16) float s_r[4][Kq], s_k[4][Kq], s_w[4][Kq], s_v[4][Kq];
    const uint32_t a_r = smem_u32(s_r), a_k = smem_u32(s_k);
    const uint32_t a_w = smem_u32(s_w), a_v = smem_u32(s_v);

    unsigned long long S2[32];
    #pragma unroll
    for (int i = 0; i < 32; i++) S2[i] = 0ull;

    auto issue = [&](int t) {
        int st = t & 3;
        int tr = dir ? (Tq - 1 - t) : t;
        size_t off = base + (size_t)tr * Dq + j;
        uint32_t so = (uint32_t)(st * Kq + j) * 4;
        cp4(a_r + so, &g_r[off]);
        cp4(a_k + so, &g_k[off]);
        cp4(a_w + so, &g_ww[off]);
        cp4(a_v + so, &g_v[off]);
        CP_COMMIT();
    };

    issue(0); issue(1); issue(2);

    for (int t = 0; t < Tq; t++) {
        int st = t & 3;
        CP_WAIT(2);
        __syncthreads();
        if (t + 3 < Tq) issue(t + 3);

        float vj = s_v[st][j];
        unsigned long long v2 = pk2(vj, vj);
        const ulonglong2* r2p = (const ulonglong2*)s_r[st];
        const ulonglong2* k2p = (const ulonglong2*)s_k[st];
        const ulonglong2* w2p = (const ulonglong2*)s_w[st];

        unsigned long long ya = 0ull, yb = 0ull, yc = 0ull, yd = 0ull;

        if (dir == 0) {
            #pragma unroll
            for (int q = 0; q < 16; q += 2) {
                ulonglong2 rq = r2p[q], kq = k2p[q], wq = w2p[q];
                ulonglong2 rq1 = r2p[q+1], kq1 = k2p[q+1], wq1 = w2p[q+1];
                S2[2*q+0] = fma2v(wq.x, S2[2*q+0], mul2(kq.x, v2));
                ya = fma2v(rq.x, S2[2*q+0], ya);
                S2[2*q+1] = fma2v(wq.y, S2[2*q+1], mul2(kq.y, v2));
                yb = fma2v(rq.y, S2[2*q+1], yb);
                S2[2*q+2] = fma2v(wq1.x, S2[2*q+2], mul2(kq1.x, v2));
                yc = fma2v(rq1.x, S2[2*q+2], yc);
                S2[2*q+3] = fma2v(wq1.y, S2[2*q+3], mul2(kq1.y, v2));
                yd = fma2v(rq1.y, S2[2*q+3], yd);
            }
        } else {
            #pragma unroll
            for (int q = 0; q < 16; q += 2) {
                ulonglong2 rq = r2p[q], kq = k2p[q], wq = w2p[q];
                ulonglong2 rq1 = r2p[q+1], kq1 = k2p[q+1], wq1 = w2p[q+1];
                ya = fma2v(rq.x, S2[2*q+0], ya);
                S2[2*q+0] = mul2(wq.x, fma2v(kq.x, v2, S2[2*q+0]));
                yb = fma2v(rq.y, S2[2*q+1], yb);
                S2[2*q+1] = mul2(wq.y, fma2v(kq.y, v2, S2[2*q+1]));
                yc = fma2v(rq1.x, S2[2*q+2], yc);
                S2[2*q+2] = mul2(wq1.x, fma2v(kq1.x, v2, S2[2*q+2]));
                yd = fma2v(rq1.y, S2[2*q+3], yd);
                S2[2*q+3] = mul2(wq1.y, fma2v(kq1.y, v2, S2[2*q+3]));
            }
        }

        float y0, y1, y2, y3, y4, y5, y6, y7;
        unpk2(ya, y0, y1); unpk2(yb, y2, y3);
        unpk2(yc, y4, y5); unpk2(yd, y6, y7);
        float y = ((y0 + y1) + (y2 + y3)) + ((y4 + y5) + (y6 + y7));

        int tr = dir ? (Tq - 1 - t) : t;
        size_t off = base + (size_t)tr * Dq + j;
        if (dir == 0) g_yf[off] = y;
        else          g_yb[off] = y;
    }
}

// ---------------- groupnorm + output gate + silu-gate (→ z hi/lo) ---------------
__global__ void __launch_bounds__(128) gn_kernel(const float* __restrict__ ln_w,
                                                 const float* __restrict__ ln_b)
{
    int gidx = blockIdx.x * 4 + (threadIdx.x >> 5);
    int lane = threadIdx.x & 31;
    int bt = gidx / Hq, h = gidx % Hq;
    size_t rowbase = (size_t)bt * Dq + (size_t)h * Kq;
    size_t i0 = rowbase + lane, i1 = rowbase + lane + 32;

    float a = (g_yf[i0] + g_yb[i0]) * g_gate[i0];
    float c = (g_yf[i1] + g_yb[i1]) * g_gate[i1];
    float s = a + c, sq = a * a + c * c;
    #pragma unroll
    for (int o = 16; o; o >>= 1) {
        s  += __shfl_xor_sync(0xffffffffu, s,  o);
        sq += __shfl_xor_sync(0xffffffffu, sq, o);
    }
    float mean = s * (1.f / 64.f);
    float var  = sq * (1.f / 64.f) - mean * mean;
    float rstd = rsqrtf(var + 6.4e-4f);
    int d0 = h * Kq + lane, d1 = d0 + 32;
    float z0 = ((a - mean) * rstd * ln_w[d0] + ln_b[d0]) * g_g[i0];
    float z1 = ((c - mean) * rstd * ln_w[d1] + ln_b[d1]) * g_g[i1];
    __nv_bfloat16 h0 = __float2bfloat16(z0);
    __nv_bfloat16 h1 = __float2bfloat16(z1);
    g_zh[i0] = h0; g_zl[i0] = __float2bfloat16(z0 - __bfloat162float(h0));
    g_zh[i1] = h1; g_zl[i1] = __float2bfloat16(z1 - __bfloat162float(h1));
}

// ---------------- launch --------------------------------------------------------
extern "C" void kernel_launch(void* const* d_in, const int* in_sizes, int n_in,
                              void* d_out, int out_size)
{
    const float* x          = (const float*)d_in[0];
    const float* conv_w     = (const float*)d_in[1];
    const float* maa_x      = (const float*)d_in[2];
    const float* maa_w      = (const float*)d_in[3];
    const float* maa_k      = (const float*)d_in[4];
    const float* maa_v      = (const float*)d_in[5];
    const float* maa_r      = (const float*)d_in[6];
    const float* maa_g      = (const float*)d_in[7];
    const float* maa_w1     = (const float*)d_in[8];
    const float* maa_w2     = (const float*)d_in[9];
    const float* time_decay = (const float*)d_in[10];
    const float* decay_w1   = (const float*)d_in[11];
    const float* decay_w2   = (const float*)d_in[12];
    const float* Wr         = (const float*)d_in[13];
    const float* Wk         = (const float*)d_in[14];
    const float* Wv         = (const float*)d_in[15];
    const float* Wg         = (const float*)d_in[16];
    const float* Wo         = (const float*)d_in[17];
    const float* ln_w       = (const float*)d_in[18];
    const float* ln_b       = (const float*)d_in[19];
    const float* gate_w     = (const float*)d_in[20];
    const float* gate_b     = (const float*)d_in[21];
    float* out = (float*)d_out;

    float *p_xxx, *p_t5, *p_xw, *p_r, *p_k, *p_v, *p_g, *p_h, *p_ww, *p_gate;
    __nv_bfloat16 *p_dxh, *p_dxl, *p_xkh, *p_xkl, *p_xvh, *p_xvl;
    __nv_bfloat16 *p_xrh, *p_xrl, *p_xgh, *p_xgl, *p_zh, *p_zl, *p_wh, *p_wl;
    cudaGetSymbolAddress((void**)&p_xxx,  g_xxx);
    cudaGetSymbolAddress((void**)&p_t5,   g_t5);
    cudaGetSymbolAddress((void**)&p_xw,   g_xw);
    cudaGetSymbolAddress((void**)&p_r,    g_r);
    cudaGetSymbolAddress((void**)&p_k,    g_k);
    cudaGetSymbolAddress((void**)&p_v,    g_v);
    cudaGetSymbolAddress((void**)&p_g,    g_g);
    cudaGetSymbolAddress((void**)&p_h,    g_hbuf);
    cudaGetSymbolAddress((void**)&p_ww,   g_ww);
    cudaGetSymbolAddress((void**)&p_gate, g_gate);
    cudaGetSymbolAddress((void**)&p_dxh,  g_dxh);
    cudaGetSymbolAddress((void**)&p_dxl,  g_dxl);
    cudaGetSymbolAddress((void**)&p_xkh,  g_xkh);
    cudaGetSymbolAddress((void**)&p_xkl,  g_xkl);
    cudaGetSymbolAddress((void**)&p_xvh,  g_xvh);
    cudaGetSymbolAddress((void**)&p_xvl,  g_xvl);
    cudaGetSymbolAddress((void**)&p_xrh,  g_xrh);
    cudaGetSymbolAddress((void**)&p_xrl,  g_xrl);
    cudaGetSymbolAddress((void**)&p_xgh,  g_xgh);
    cudaGetSymbolAddress((void**)&p_xgl,  g_xgl);
    cudaGetSymbolAddress((void**)&p_zh,   g_zh);
    cudaGetSymbolAddress((void**)&p_zl,   g_zl);
    cudaGetSymbolAddress((void**)&p_wh,   g_wh);
    cudaGetSymbolAddress((void**)&p_wl,   g_wl);

    cudaFuncSetAttribute(hmma_gemm<TEPI_NONE>, cudaFuncAttributeMaxDynamicSharedMemorySize, HM_SMEM);
    cudaFuncSetAttribute(hmma_gemm<TEPI_SILU>, cudaFuncAttributeMaxDynamicSharedMemorySize, HM_SMEM);
    cudaFuncSetAttribute(hmma_gemm<TEPI_GATE>, cudaFuncAttributeMaxDynamicSharedMemorySize, HM_SMEM);

    // 0) conv / dx hi/lo / xxx
    {
        int threads = 256;
        int blocks  = (int)((BTDq + threads - 1) / threads);
        conv_kernel<<<blocks, threads>>>(x, conv_w, maa_x);
    }

    // 1) weight transpose + split (slots: Wr,Wk,Wv,Wg,gate_w,Wo)
    {
        dim3 g(32, 32, 6);
        wsplit_kernel<<<g, 256>>>(Wr, Wk, Wv, Wg, gate_w, Wo);
    }

    dim3 blk(256);
    dim3 grid_t5(2, Mq / BMt);
    dim3 grid_64(1, Mq / BMt);
    dim3 grid_dec(Dq / BNt, Mq / BMt);
    dim3 hm_grid(8, Mq / 128);

    // 2) t5 = tanh(xxx @ maa_w1)
    sgemm<EPI_TANH><<<grid_t5, blk>>>(p_xxx, Dq, maa_w1, 160, p_t5, 160,
                                      160, Dq, nullptr);

    // 3) fused token-mix: xw fp32; xk/xv/xr/xg as bf16 hi/lo
    {
        dim3 g(Dq / 128, Mq / 64);
        mix5_kernel<<<g, 256>>>(maa_w2, x, maa_w, maa_k, maa_v, maa_r, maa_g);
    }

    const size_t WS = 1024 * 1024;
    // 4) big projections on tensor cores (HMMA mma.sync); ncu -s 5 lands on #5
    hmma_gemm<TEPI_NONE><<<hm_grid, 256, HM_SMEM>>>(p_xrh, p_xrl, p_wh + 0*WS, p_wl + 0*WS, p_r, nullptr);
    hmma_gemm<TEPI_NONE><<<hm_grid, 256, HM_SMEM>>>(p_xkh, p_xkl, p_wh + 1*WS, p_wl + 1*WS, p_k, nullptr);
    hmma_gemm<TEPI_NONE><<<hm_grid, 256, HM_SMEM>>>(p_xvh, p_xvl, p_wh + 2*WS, p_wl + 2*WS, p_v, nullptr);
    hmma_gemm<TEPI_SILU><<<hm_grid, 256, HM_SMEM>>>(p_xgh, p_xgl, p_wh + 3*WS, p_wl + 3*WS, p_g, nullptr);
    hmma_gemm<TEPI_GATE><<<hm_grid, 256, HM_SMEM>>>(p_dxh, p_dxl, p_wh + 4*WS, p_wl + 4*WS, p_gate, gate_b);

    // 5) decay MLP (scalar)
    sgemm<EPI_TANH><<<grid_64, blk>>>(p_xw, Dq, decay_w1, 64, p_h, 64,
                                      64, Dq, nullptr);
    sgemm<EPI_DECAY><<<grid_dec, blk>>>(p_h, 64, decay_w2, Dq, p_ww, Dq,
                                        Dq, 64, time_decay);

    // 6) bidirectional recurrence
    {
        dim3 g(Bq * Hq, 2);
        wkv_kernel<<<g, 64>>>();
    }

    // 7) gate + groupnorm + silu-gate → z hi/lo
    gn_kernel<<<(Mq * Hq) / 4, 128>>>(ln_w, ln_b);

    // 8) out = z @ Wo (HMMA)
    hmma_gemm<TEPI_NONE><<<hm_grid, 256, HM_SMEM>>>(p_zh, p_zl, p_wh + 5*WS, p_wl + 5*WS, out, nullptr);
}